// round 1
// baseline (speedup 1.0000x reference)
#include <cuda_runtime.h>
#include <math.h>

#define T_LEN   64
#define BATCH   1024
#define VOCAB   128
#define HID     512
#define G4      2048
#define IMGFEAT 3600

// ---------------- scratch (static device globals; no allocation) ----------------
__device__ float g_a1[BATCH * 8 * 32 * 32];      //  32 MB  conv1+pool out
__device__ float g_a2[BATCH * 16 * 15 * 15];     //  14 MB  conv2+pool out (== flattened e input)
__device__ float g_e [BATCH * HID];              //   2 MB  image embedding
__device__ float g_xg[(size_t)T_LEN * BATCH * G4]; // 512 MB precomputed input gates
__device__ float g_h0[BATCH * HID];              // h double buffer 0
__device__ float g_h1[BATCH * HID];              // h double buffer 1
__device__ float g_c [BATCH * HID];              // cell state
__device__ float g_hs[(size_t)T_LEN * BATCH * HID]; // 128 MB all hidden states

// ---------------- init ----------------
__global__ void zero_hc() {
    int i = blockIdx.x * blockDim.x + threadIdx.x;
    if (i < BATCH * HID) { g_h0[i] = 0.f; g_c[i] = 0.f; }
}

// ---------------- conv1 (1->8, 3x3, pad1) + relu + 2x2 maxpool : 64x64 -> 32x32 ----------------
__global__ void conv1_pool(const float* __restrict__ img,
                           const float* __restrict__ w,
                           const float* __restrict__ b) {
    int idx = blockIdx.x * blockDim.x + threadIdx.x;
    if (idx >= BATCH * 8 * 32 * 32) return;
    int px = idx & 31;
    int py = (idx >> 5) & 31;
    int oc = (idx >> 10) & 7;
    int bb = idx >> 13;
    const float* im = img + (size_t)bb * 64 * 64;
    const float* wk = w + oc * 9;
    float bias = b[oc];
    float m = -INFINITY;
#pragma unroll
    for (int dy = 0; dy < 2; dy++) {
#pragma unroll
        for (int dx = 0; dx < 2; dx++) {
            int y = py * 2 + dy, x = px * 2 + dx;
            float acc = bias;
#pragma unroll
            for (int ky = 0; ky < 3; ky++) {
                int iy = y + ky - 1;
                if ((unsigned)iy < 64u) {
#pragma unroll
                    for (int kx = 0; kx < 3; kx++) {
                        int ix = x + kx - 1;
                        if ((unsigned)ix < 64u)
                            acc += im[iy * 64 + ix] * wk[ky * 3 + kx];
                    }
                }
            }
            m = fmaxf(m, fmaxf(acc, 0.f));
        }
    }
    g_a1[idx] = m;
}

// ---------------- conv2 (8->16, 5x5, pad1) + relu + 2x2 maxpool : 32x32 -> 30x30 -> 15x15 ----------------
__global__ void conv2_pool(const float* __restrict__ w,
                           const float* __restrict__ b) {
    __shared__ float ws[16 * 8 * 25];
    for (int i = threadIdx.x; i < 16 * 8 * 25; i += blockDim.x) ws[i] = w[i];
    __syncthreads();
    int idx = blockIdx.x * blockDim.x + threadIdx.x;
    if (idx >= BATCH * 16 * 15 * 15) return;
    int px = idx % 15;
    int t  = idx / 15;
    int py = t % 15; t /= 15;
    int oc = t & 15;
    int bb = t >> 4;
    const float* a1b = g_a1 + (size_t)bb * 8 * 32 * 32;
    float bias = b[oc];
    float m = -INFINITY;
#pragma unroll
    for (int dy = 0; dy < 2; dy++) {
#pragma unroll
        for (int dx = 0; dx < 2; dx++) {
            int oy = py * 2 + dy, ox = px * 2 + dx;   // conv out coords in 30x30
            float acc = bias;
            for (int ic = 0; ic < 8; ic++) {
                const float* wp = ws + (oc * 8 + ic) * 25;
                const float* ap = a1b + ic * 1024;
#pragma unroll
                for (int ky = 0; ky < 5; ky++) {
                    int iy = oy + ky - 1;
                    if ((unsigned)iy < 32u) {
#pragma unroll
                        for (int kx = 0; kx < 5; kx++) {
                            int ix = ox + kx - 1;
                            if ((unsigned)ix < 32u)
                                acc += ap[iy * 32 + ix] * wp[ky * 5 + kx];
                        }
                    }
                }
            }
            m = fmaxf(m, fmaxf(acc, 0.f));
        }
    }
    g_a2[idx] = m;
}

// ---------------- imgfc: e = relu(a2[1024,3600] @ w[3600,512] + b) ----------------
__global__ void imgfc_gemm(const float* __restrict__ W,
                           const float* __restrict__ bias) {
    __shared__ float As[16][64 + 1];
    __shared__ float Bs[16][64];
    const int K = IMGFEAT, N = HID;
    int tid = threadIdx.x;
    int tx = tid & 15, ty = tid >> 4;
    int bm = blockIdx.y * 64, bn = blockIdx.x * 64;
    float acc[4][4] = {};
    for (int k0 = 0; k0 < K; k0 += 16) {
#pragma unroll
        for (int i = 0; i < 4; i++) {
            int idx = tid + i * 256;
            int r = idx >> 4, c = idx & 15;
            As[c][r] = g_a2[(size_t)(bm + r) * K + k0 + c];
        }
#pragma unroll
        for (int i = 0; i < 4; i++) {
            int idx = tid + i * 256;
            int r = idx >> 6, c = idx & 63;
            Bs[r][c] = W[(size_t)(k0 + r) * N + bn + c];
        }
        __syncthreads();
#pragma unroll
        for (int kk = 0; kk < 16; kk++) {
            float a0 = As[kk][ty * 4 + 0], a1 = As[kk][ty * 4 + 1];
            float a2 = As[kk][ty * 4 + 2], a3 = As[kk][ty * 4 + 3];
            float b0 = Bs[kk][tx * 4 + 0], b1 = Bs[kk][tx * 4 + 1];
            float b2 = Bs[kk][tx * 4 + 2], b3 = Bs[kk][tx * 4 + 3];
            acc[0][0] += a0 * b0; acc[0][1] += a0 * b1; acc[0][2] += a0 * b2; acc[0][3] += a0 * b3;
            acc[1][0] += a1 * b0; acc[1][1] += a1 * b1; acc[1][2] += a1 * b2; acc[1][3] += a1 * b3;
            acc[2][0] += a2 * b0; acc[2][1] += a2 * b1; acc[2][2] += a2 * b2; acc[2][3] += a2 * b3;
            acc[3][0] += a3 * b0; acc[3][1] += a3 * b1; acc[3][2] += a3 * b2; acc[3][3] += a3 * b3;
        }
        __syncthreads();
    }
#pragma unroll
    for (int r = 0; r < 4; r++) {
        int m = bm + ty * 4 + r;
#pragma unroll
        for (int c = 0; c < 4; c++) {
            int n = bn + tx * 4 + c;
            float v = acc[r][c] + bias[n];
            g_e[(size_t)m * HID + n] = fmaxf(v, 0.f);
        }
    }
}

// ---------------- xg = inp[65536,128] @ xh_w[128,2048] + xh_b  (+ img4 on t==0 rows) ----------------
__global__ void xg_gemm(const float* __restrict__ A,
                        const float* __restrict__ W,
                        const float* __restrict__ bias) {
    __shared__ float As[16][64 + 1];
    __shared__ float Bs[16][64];
    const int K = VOCAB, N = G4;
    int tid = threadIdx.x;
    int tx = tid & 15, ty = tid >> 4;
    int bm = blockIdx.y * 64, bn = blockIdx.x * 64;
    float acc[4][4] = {};
    for (int k0 = 0; k0 < K; k0 += 16) {
#pragma unroll
        for (int i = 0; i < 4; i++) {
            int idx = tid + i * 256;
            int r = idx >> 4, c = idx & 15;
            As[c][r] = A[(size_t)(bm + r) * K + k0 + c];
        }
#pragma unroll
        for (int i = 0; i < 4; i++) {
            int idx = tid + i * 256;
            int r = idx >> 6, c = idx & 63;
            Bs[r][c] = W[(size_t)(k0 + r) * N + bn + c];
        }
        __syncthreads();
#pragma unroll
        for (int kk = 0; kk < 16; kk++) {
            float a0 = As[kk][ty * 4 + 0], a1 = As[kk][ty * 4 + 1];
            float a2 = As[kk][ty * 4 + 2], a3 = As[kk][ty * 4 + 3];
            float b0 = Bs[kk][tx * 4 + 0], b1 = Bs[kk][tx * 4 + 1];
            float b2 = Bs[kk][tx * 4 + 2], b3 = Bs[kk][tx * 4 + 3];
            acc[0][0] += a0 * b0; acc[0][1] += a0 * b1; acc[0][2] += a0 * b2; acc[0][3] += a0 * b3;
            acc[1][0] += a1 * b0; acc[1][1] += a1 * b1; acc[1][2] += a1 * b2; acc[1][3] += a1 * b3;
            acc[2][0] += a2 * b0; acc[2][1] += a2 * b1; acc[2][2] += a2 * b2; acc[2][3] += a2 * b3;
            acc[3][0] += a3 * b0; acc[3][1] += a3 * b1; acc[3][2] += a3 * b2; acc[3][3] += a3 * b3;
        }
        __syncthreads();
    }
#pragma unroll
    for (int r = 0; r < 4; r++) {
        int m = bm + ty * 4 + r;
#pragma unroll
        for (int c = 0; c < 4; c++) {
            int n = bn + tx * 4 + c;
            float v = acc[r][c] + bias[n];
            if (m < BATCH) v += g_e[(size_t)m * HID + (n & (HID - 1))]; // t==0 rows: += img4
            g_xg[(size_t)m * N + n] = v;
        }
    }
}

// ---------------- one LSTM step: gates = xg[t] + h @ hh_w + hh_b ; cell update fused ----------------
__global__ void lstm_step(const float* __restrict__ hh_w,
                          const float* __restrict__ hh_b,
                          int t) {
    __shared__ float As[16][64 + 1];
    __shared__ float Bs[4][16][64];
    int tid = threadIdx.x;
    int tx = tid & 15, ty = tid >> 4;
    int bm = blockIdx.y * 64;
    int bn = blockIdx.x * 64;            // 0..448, within a 512-wide gate chunk
    const float* hin  = (t & 1) ? g_h1 : g_h0;
    float*       hout = (t & 1) ? g_h0 : g_h1;
    const float* xg_t = g_xg + (size_t)t * BATCH * G4;

    float acc[4][4][4] = {};             // [gate][row][col]
    for (int k0 = 0; k0 < HID; k0 += 16) {
#pragma unroll
        for (int i = 0; i < 4; i++) {
            int idx = tid + i * 256;
            int r = idx >> 4, c = idx & 15;
            As[c][r] = hin[(size_t)(bm + r) * HID + k0 + c];
        }
#pragma unroll
        for (int i = 0; i < 16; i++) {
            int idx = tid + i * 256;          // 4096 elements
            int g = idx >> 10;
            int rem = idx & 1023;
            int r = rem >> 6, c = rem & 63;
            Bs[g][r][c] = hh_w[(size_t)(k0 + r) * G4 + g * HID + bn + c];
        }
        __syncthreads();
#pragma unroll
        for (int kk = 0; kk < 16; kk++) {
            float a[4];
#pragma unroll
            for (int r = 0; r < 4; r++) a[r] = As[kk][ty * 4 + r];
#pragma unroll
            for (int g = 0; g < 4; g++) {
                float b[4];
#pragma unroll
                for (int c = 0; c < 4; c++) b[c] = Bs[g][kk][tx * 4 + c];
#pragma unroll
                for (int r = 0; r < 4; r++)
#pragma unroll
                    for (int c = 0; c < 4; c++)
                        acc[g][r][c] += a[r] * b[c];
            }
        }
        __syncthreads();
    }

#pragma unroll
    for (int r = 0; r < 4; r++) {
        int m = bm + ty * 4 + r;
        size_t mrow = (size_t)m * G4;
#pragma unroll
        for (int c = 0; c < 4; c++) {
            int n = bn + tx * 4 + c;
            float gi = acc[0][r][c] + xg_t[mrow + 0 * HID + n] + hh_b[0 * HID + n];
            float gf = acc[1][r][c] + xg_t[mrow + 1 * HID + n] + hh_b[1 * HID + n];
            float gg = acc[2][r][c] + xg_t[mrow + 2 * HID + n] + hh_b[2 * HID + n];
            float go = acc[3][r][c] + xg_t[mrow + 3 * HID + n] + hh_b[3 * HID + n];
            float i_ = 1.f / (1.f + expf(-gi));
            float f_ = 1.f / (1.f + expf(-gf));
            float g_ = tanhf(gg);
            float o_ = 1.f / (1.f + expf(-go));
            size_t hi = (size_t)m * HID + n;
            float cn = f_ * g_c[hi] + i_ * g_;
            float hn = o_ * tanhf(cn);
            g_c[hi]  = cn;
            hout[hi] = hn;
            g_hs[(size_t)t * BATCH * HID + hi] = hn;
        }
    }
}

// ---------------- logits = hs[65536,512] @ out_w[512,128] + b ; fused log_softmax ----------------
__global__ void out_logsoftmax(const float* __restrict__ W,
                               const float* __restrict__ bias,
                               float* __restrict__ out) {
    __shared__ float As[16][32 + 1];
    __shared__ float Bs[16][128];
    __shared__ float Ls[32][128 + 1];
    int tid = threadIdx.x;
    int tx = tid & 31, ty = tid >> 5;     // 32 x 8 threads, 4x4 microtile
    int bm = blockIdx.x * 32;
    float acc[4][4] = {};
    for (int k0 = 0; k0 < HID; k0 += 16) {
#pragma unroll
        for (int i = 0; i < 2; i++) {
            int idx = tid + i * 256;
            int r = idx >> 4, c = idx & 15;
            As[c][r] = g_hs[(size_t)(bm + r) * HID + k0 + c];
        }
#pragma unroll
        for (int i = 0; i < 8; i++) {
            int idx = tid + i * 256;
            int r = idx >> 7, c = idx & 127;
            Bs[r][c] = W[(size_t)(k0 + r) * VOCAB + c];
        }
        __syncthreads();
#pragma unroll
        for (int kk = 0; kk < 16; kk++) {
            float a0 = As[kk][ty * 4 + 0], a1 = As[kk][ty * 4 + 1];
            float a2 = As[kk][ty * 4 + 2], a3 = As[kk][ty * 4 + 3];
            float b0 = Bs[kk][tx * 4 + 0], b1 = Bs[kk][tx * 4 + 1];
            float b2 = Bs[kk][tx * 4 + 2], b3 = Bs[kk][tx * 4 + 3];
            acc[0][0] += a0 * b0; acc[0][1] += a0 * b1; acc[0][2] += a0 * b2; acc[0][3] += a0 * b3;
            acc[1][0] += a1 * b0; acc[1][1] += a1 * b1; acc[1][2] += a1 * b2; acc[1][3] += a1 * b3;
            acc[2][0] += a2 * b0; acc[2][1] += a2 * b1; acc[2][2] += a2 * b2; acc[2][3] += a2 * b3;
            acc[3][0] += a3 * b0; acc[3][1] += a3 * b1; acc[3][2] += a3 * b2; acc[3][3] += a3 * b3;
        }
        __syncthreads();
    }
#pragma unroll
    for (int r = 0; r < 4; r++)
#pragma unroll
        for (int c = 0; c < 4; c++)
            Ls[ty * 4 + r][tx * 4 + c] = acc[r][c] + bias[tx * 4 + c];
    __syncthreads();

    int warp = tid >> 5, lane = tid & 31;
#pragma unroll
    for (int r = 0; r < 4; r++) {
        int row = warp * 4 + r;
        float v0 = Ls[row][lane], v1 = Ls[row][lane + 32];
        float v2 = Ls[row][lane + 64], v3 = Ls[row][lane + 96];
        float mx = fmaxf(fmaxf(v0, v1), fmaxf(v2, v3));
#pragma unroll
        for (int off = 16; off; off >>= 1) mx = fmaxf(mx, __shfl_xor_sync(0xffffffffu, mx, off));
        float s = expf(v0 - mx) + expf(v1 - mx) + expf(v2 - mx) + expf(v3 - mx);
#pragma unroll
        for (int off = 16; off; off >>= 1) s += __shfl_xor_sync(0xffffffffu, s, off);
        float lse = mx + logf(s);
        size_t base = (size_t)(bm + row) * VOCAB;
        out[base + lane]      = v0 - lse;
        out[base + lane + 32] = v1 - lse;
        out[base + lane + 64] = v2 - lse;
        out[base + lane + 96] = v3 - lse;
    }
}

// ---------------- launch ----------------
extern "C" void kernel_launch(void* const* d_in, const int* in_sizes, int n_in,
                              void* d_out, int out_size) {
    const float* inp = (const float*)d_in[0];
    const float* img = (const float*)d_in[1];
    const float* c1w = (const float*)d_in[2];
    const float* c1b = (const float*)d_in[3];
    const float* c2w = (const float*)d_in[4];
    const float* c2b = (const float*)d_in[5];
    const float* fw  = (const float*)d_in[6];
    const float* fb  = (const float*)d_in[7];
    const float* xhw = (const float*)d_in[8];
    const float* xhb = (const float*)d_in[9];
    const float* hhw = (const float*)d_in[10];
    const float* hhb = (const float*)d_in[11];
    const float* ow  = (const float*)d_in[12];
    const float* ob  = (const float*)d_in[13];
    float* out = (float*)d_out;

    zero_hc<<<(BATCH * HID) / 256, 256>>>();
    conv1_pool<<<(BATCH * 8 * 32 * 32) / 256, 256>>>(img, c1w, c1b);
    conv2_pool<<<(BATCH * 16 * 15 * 15) / 256, 256>>>(c2w, c2b);
    imgfc_gemm<<<dim3(HID / 64, BATCH / 64), 256>>>(fw, fb);
    xg_gemm<<<dim3(G4 / 64, (T_LEN * BATCH) / 64), 256>>>(inp, xhw, xhb);
    for (int t = 0; t < T_LEN; t++)
        lstm_step<<<dim3(HID / 64, BATCH / 64), 256>>>(hhw, hhb, t);
    out_logsoftmax<<<(T_LEN * BATCH) / 32, 256>>>(ow, ob, out);
}

// round 3
// speedup vs baseline: 1.6202x; 1.6202x over previous
#include <cuda_runtime.h>
#include <math.h>
#include <stdint.h>

#define T_LEN   64
#define BATCH   1024
#define VOCAB   128
#define HID     512
#define G4      2048
#define IMGFEAT 3600

// ---------------- helpers ----------------
__device__ __forceinline__ void cp16(uint32_t dst, const float* src) {
    size_t g = __cvta_generic_to_global((void*)src);
    asm volatile("cp.async.cg.shared.global [%0], [%1], 16;" :: "r"(dst), "l"(g));
}
#define CP_COMMIT() asm volatile("cp.async.commit_group;" ::: "memory")
#define CP_WAIT(n)  asm volatile("cp.async.wait_group %0;" :: "n"(n) : "memory")

__device__ __forceinline__ uint32_t smem_u32(const void* p) {
    uint32_t a;
    asm("{ .reg .u64 t; cvta.to.shared.u64 t, %1; cvt.u32.u64 %0, t; }" : "=r"(a) : "l"(p));
    return a;
}

// m16n8k8 tf32 mma (row.col), fp32 accumulate
__device__ __forceinline__ void mma_tf32(float c[4],
                                         uint32_t a0, uint32_t a1, uint32_t a2, uint32_t a3,
                                         uint32_t b0, uint32_t b1) {
    asm volatile(
        "mma.sync.aligned.m16n8k8.row.col.f32.tf32.tf32.f32 "
        "{%0,%1,%2,%3}, {%4,%5,%6,%7}, {%8,%9}, {%0,%1,%2,%3};"
        : "+f"(c[0]), "+f"(c[1]), "+f"(c[2]), "+f"(c[3])
        : "r"(a0), "r"(a1), "r"(a2), "r"(a3), "r"(b0), "r"(b1));
}

// ---------------- scratch ----------------
__device__ float g_a1[BATCH * 8 * 32 * 32];
__device__ float g_a2[BATCH * 16 * 15 * 15];
__device__ float g_e [BATCH * HID];
__device__ float g_wt[(size_t)G4 * HID];             // hh_w transposed: [2048,512] K-major
__device__ float g_xg[(size_t)T_LEN * BATCH * G4];   // xh proj + xh_b + hh_b (+ img4 at t=0)
__device__ float g_h0[BATCH * HID];                  // zeros (t=0 h input)
__device__ float g_c [BATCH * HID];
__device__ float g_hs[(size_t)T_LEN * BATCH * HID];  // h for every step (also the h chain)

// ---------------- init ----------------
__global__ void zero_hc() {
    int i = blockIdx.x * blockDim.x + threadIdx.x;
    if (i < BATCH * HID) { g_h0[i] = 0.f; g_c[i] = 0.f; }
}

// ---------------- transpose hh_w [512,2048] -> g_wt [2048,512] ----------------
__global__ void transpose_hh(const float* __restrict__ W) {
    __shared__ float ts[32][33];
    int bx = blockIdx.x * 32;  // n
    int by = blockIdx.y * 32;  // k
    int x = threadIdx.x, y = threadIdx.y;  // 32 x 8
#pragma unroll
    for (int i = 0; i < 32; i += 8)
        ts[y + i][x] = W[(size_t)(by + y + i) * G4 + bx + x];
    __syncthreads();
#pragma unroll
    for (int i = 0; i < 32; i += 8)
        g_wt[(size_t)(bx + y + i) * HID + by + x] = ts[x][y + i];
}

// ---------------- conv1 (1->8,3x3,pad1)+relu+pool ----------------
__global__ void conv1_pool(const float* __restrict__ img,
                           const float* __restrict__ w,
                           const float* __restrict__ b) {
    int idx = blockIdx.x * blockDim.x + threadIdx.x;
    if (idx >= BATCH * 8 * 32 * 32) return;
    int px = idx & 31;
    int py = (idx >> 5) & 31;
    int oc = (idx >> 10) & 7;
    int bb = idx >> 13;
    const float* im = img + (size_t)bb * 64 * 64;
    const float* wk = w + oc * 9;
    float bias = b[oc];
    float m = -INFINITY;
#pragma unroll
    for (int dy = 0; dy < 2; dy++) {
#pragma unroll
        for (int dx = 0; dx < 2; dx++) {
            int y = py * 2 + dy, x = px * 2 + dx;
            float acc = bias;
#pragma unroll
            for (int ky = 0; ky < 3; ky++) {
                int iy = y + ky - 1;
                if ((unsigned)iy < 64u) {
#pragma unroll
                    for (int kx = 0; kx < 3; kx++) {
                        int ix = x + kx - 1;
                        if ((unsigned)ix < 64u)
                            acc += im[iy * 64 + ix] * wk[ky * 3 + kx];
                    }
                }
            }
            m = fmaxf(m, fmaxf(acc, 0.f));
        }
    }
    g_a1[idx] = m;
}

// ---------------- conv2 (8->16,5x5,pad1)+relu+pool ----------------
__global__ void conv2_pool(const float* __restrict__ w,
                           const float* __restrict__ b) {
    __shared__ float ws[16 * 8 * 25];
    for (int i = threadIdx.x; i < 16 * 8 * 25; i += blockDim.x) ws[i] = w[i];
    __syncthreads();
    int idx = blockIdx.x * blockDim.x + threadIdx.x;
    if (idx >= BATCH * 16 * 15 * 15) return;
    int px = idx % 15;
    int t  = idx / 15;
    int py = t % 15; t /= 15;
    int oc = t & 15;
    int bb = t >> 4;
    const float* a1b = g_a1 + (size_t)bb * 8 * 32 * 32;
    float bias = b[oc];
    float m = -INFINITY;
#pragma unroll
    for (int dy = 0; dy < 2; dy++) {
#pragma unroll
        for (int dx = 0; dx < 2; dx++) {
            int oy = py * 2 + dy, ox = px * 2 + dx;
            float acc = bias;
            for (int ic = 0; ic < 8; ic++) {
                const float* wp = ws + (oc * 8 + ic) * 25;
                const float* ap = a1b + ic * 1024;
#pragma unroll
                for (int ky = 0; ky < 5; ky++) {
                    int iy = oy + ky - 1;
                    if ((unsigned)iy < 32u) {
#pragma unroll
                        for (int kx = 0; kx < 5; kx++) {
                            int ix = ox + kx - 1;
                            if ((unsigned)ix < 32u)
                                acc += ap[iy * 32 + ix] * wp[ky * 5 + kx];
                        }
                    }
                }
            }
            m = fmaxf(m, fmaxf(acc, 0.f));
        }
    }
    g_a2[idx] = m;
}

// ---------------- imgfc: e = relu(a2 @ W + b) ----------------
__global__ void imgfc_gemm(const float* __restrict__ W,
                           const float* __restrict__ bias) {
    __shared__ float As[16][64 + 1];
    __shared__ float Bs[16][64];
    const int K = IMGFEAT, N = HID;
    int tid = threadIdx.x;
    int tx = tid & 15, ty = tid >> 4;
    int bm = blockIdx.y * 64, bn = blockIdx.x * 64;
    float acc[4][4] = {};
    for (int k0 = 0; k0 < K; k0 += 16) {
#pragma unroll
        for (int i = 0; i < 4; i++) {
            int idx = tid + i * 256;
            int r = idx >> 4, c = idx & 15;
            As[c][r] = g_a2[(size_t)(bm + r) * K + k0 + c];
        }
#pragma unroll
        for (int i = 0; i < 4; i++) {
            int idx = tid + i * 256;
            int r = idx >> 6, c = idx & 63;
            Bs[r][c] = W[(size_t)(k0 + r) * N + bn + c];
        }
        __syncthreads();
#pragma unroll
        for (int kk = 0; kk < 16; kk++) {
            float a0 = As[kk][ty * 4 + 0], a1 = As[kk][ty * 4 + 1];
            float a2 = As[kk][ty * 4 + 2], a3 = As[kk][ty * 4 + 3];
            float b0 = Bs[kk][tx * 4 + 0], b1 = Bs[kk][tx * 4 + 1];
            float b2 = Bs[kk][tx * 4 + 2], b3 = Bs[kk][tx * 4 + 3];
            acc[0][0] += a0 * b0; acc[0][1] += a0 * b1; acc[0][2] += a0 * b2; acc[0][3] += a0 * b3;
            acc[1][0] += a1 * b0; acc[1][1] += a1 * b1; acc[1][2] += a1 * b2; acc[1][3] += a1 * b3;
            acc[2][0] += a2 * b0; acc[2][1] += a2 * b1; acc[2][2] += a2 * b2; acc[2][3] += a2 * b3;
            acc[3][0] += a3 * b0; acc[3][1] += a3 * b1; acc[3][2] += a3 * b2; acc[3][3] += a3 * b3;
        }
        __syncthreads();
    }
#pragma unroll
    for (int r = 0; r < 4; r++) {
        int m = bm + ty * 4 + r;
#pragma unroll
        for (int c = 0; c < 4; c++) {
            int n = bn + tx * 4 + c;
            float v = acc[r][c] + bias[n];
            g_e[(size_t)m * HID + n] = fmaxf(v, 0.f);
        }
    }
}

// ---------------- xg = inp @ xh_w + xh_b + hh_b (+ img4 on t==0 rows) ----------------
__global__ void xg_gemm(const float* __restrict__ A,
                        const float* __restrict__ W,
                        const float* __restrict__ bias,
                        const float* __restrict__ hhb) {
    __shared__ float As[16][64 + 1];
    __shared__ float Bs[16][64];
    const int K = VOCAB, N = G4;
    int tid = threadIdx.x;
    int tx = tid & 15, ty = tid >> 4;
    int bm = blockIdx.y * 64, bn = blockIdx.x * 64;
    float acc[4][4] = {};
    for (int k0 = 0; k0 < K; k0 += 16) {
#pragma unroll
        for (int i = 0; i < 4; i++) {
            int idx = tid + i * 256;
            int r = idx >> 4, c = idx & 15;
            As[c][r] = A[(size_t)(bm + r) * K + k0 + c];
        }
#pragma unroll
        for (int i = 0; i < 4; i++) {
            int idx = tid + i * 256;
            int r = idx >> 6, c = idx & 63;
            Bs[r][c] = W[(size_t)(k0 + r) * N + bn + c];
        }
        __syncthreads();
#pragma unroll
        for (int kk = 0; kk < 16; kk++) {
            float a0 = As[kk][ty * 4 + 0], a1 = As[kk][ty * 4 + 1];
            float a2 = As[kk][ty * 4 + 2], a3 = As[kk][ty * 4 + 3];
            float b0 = Bs[kk][tx * 4 + 0], b1 = Bs[kk][tx * 4 + 1];
            float b2 = Bs[kk][tx * 4 + 2], b3 = Bs[kk][tx * 4 + 3];
            acc[0][0] += a0 * b0; acc[0][1] += a0 * b1; acc[0][2] += a0 * b2; acc[0][3] += a0 * b3;
            acc[1][0] += a1 * b0; acc[1][1] += a1 * b1; acc[1][2] += a1 * b2; acc[1][3] += a1 * b3;
            acc[2][0] += a2 * b0; acc[2][1] += a2 * b1; acc[2][2] += a2 * b2; acc[2][3] += a2 * b3;
            acc[3][0] += a3 * b0; acc[3][1] += a3 * b1; acc[3][2] += a3 * b2; acc[3][3] += a3 * b3;
        }
        __syncthreads();
    }
#pragma unroll
    for (int r = 0; r < 4; r++) {
        int m = bm + ty * 4 + r;
#pragma unroll
        for (int c = 0; c < 4; c++) {
            int n = bn + tx * 4 + c;
            float v = acc[r][c] + bias[n] + hhb[n];
            if (m < BATCH) v += g_e[(size_t)m * HID + (n & (HID - 1))];
            g_xg[(size_t)m * N + n] = v;
        }
    }
}

// ---------------- LSTM step: tf32 mma.sync GEMM + fused cell update ----------------
// Grid (16, 8): blockIdx.x -> 32-wide column slice within each gate,
//               blockIdx.y -> 128-row M tile. 256 threads (8 warps).
// Warp w: wm = w&1 (64-row half), wn = w>>1 (8-col group). Each warp computes
// 4 m-tiles (m16) x 1 n-tile (n8) x 4 gates, K=512 in 16 cp.async chunks of 32.
#define A_STRIDE 36
#define ABUF_FLOATS (128 * A_STRIDE)             // 4608
#define BBUF_FLOATS (4 * 32 * A_STRIDE)          // 4608
#define BUF_FLOATS  (ABUF_FLOATS + BBUF_FLOATS)  // 9216 floats = 36864 B
#define LSTM_SMEM   (2 * BUF_FLOATS * 4)         // 73728 B

__global__ void __launch_bounds__(256, 1)
lstm_step_mma(int t) {
    extern __shared__ float sm[];
    const uint32_t sb = smem_u32(sm);
    const int tid = threadIdx.x;
    const int lane = tid & 31, wid = tid >> 5;
    const int wm = wid & 1, wn = wid >> 1;
    const int gq = lane >> 2, tq = lane & 3;
    const int m0 = blockIdx.y * 128;
    const int n0 = blockIdx.x * 32;              // within-gate column offset

    const float* hin = (t == 0) ? g_h0 : (g_hs + (size_t)(t - 1) * BATCH * HID);
    float* hout = g_hs + (size_t)t * BATCH * HID;

    float acc[4][4][4];                          // [gate][mtile][creg]
#pragma unroll
    for (int g = 0; g < 4; g++)
#pragma unroll
        for (int mt = 0; mt < 4; mt++)
#pragma unroll
            for (int j = 0; j < 4; j++) acc[g][mt][j] = 0.f;

    // ---- async-load one 32-wide K chunk into buffer p ----
    auto load_chunk = [&](int k0, int p) {
        uint32_t base = sb + (uint32_t)p * BUF_FLOATS * 4;
#pragma unroll
        for (int j = 0; j < 4; j++) {            // A: 128 rows x 8 float4
            int idx = tid + j * 256;
            int r = idx >> 3, c4 = idx & 7;
            cp16(base + r * (A_STRIDE * 4) + c4 * 16,
                 hin + (size_t)(m0 + r) * HID + k0 + c4 * 4);
        }
        base += ABUF_FLOATS * 4;
#pragma unroll
        for (int j = 0; j < 4; j++) {            // B: 4 gates x 32 n-rows x 8 float4
            int idx = tid + j * 256;
            int gn = idx >> 3, c4 = idx & 7;     // gn = g*32+n
            int g = gn >> 5, n = gn & 31;
            cp16(base + gn * (A_STRIDE * 4) + c4 * 16,
                 g_wt + (size_t)(g * HID + n0 + n) * HID + k0 + c4 * 4);
        }
        CP_COMMIT();
    };

    load_chunk(0, 0);

    for (int i = 0; i < 16; i++) {
        if (i + 1 < 16) { load_chunk((i + 1) * 32, (i + 1) & 1); CP_WAIT(1); }
        else            { CP_WAIT(0); }
        __syncthreads();

        const float* Ab = sm + (size_t)(i & 1) * BUF_FLOATS;
        const float* Bb = Ab + ABUF_FLOATS;
#pragma unroll
        for (int ks = 0; ks < 4; ks++) {
            const int kb = ks * 8;
            uint32_t afr[4][4];
#pragma unroll
            for (int mt = 0; mt < 4; mt++) {
                int r0 = wm * 64 + mt * 16 + gq;
                afr[mt][0] = __float_as_uint(Ab[(r0    ) * A_STRIDE + kb + tq    ]);
                afr[mt][1] = __float_as_uint(Ab[(r0 + 8) * A_STRIDE + kb + tq    ]);
                afr[mt][2] = __float_as_uint(Ab[(r0    ) * A_STRIDE + kb + tq + 4]);
                afr[mt][3] = __float_as_uint(Ab[(r0 + 8) * A_STRIDE + kb + tq + 4]);
            }
#pragma unroll
            for (int g = 0; g < 4; g++) {
                int nrow = g * 32 + wn * 8 + gq;
                uint32_t b0 = __float_as_uint(Bb[nrow * A_STRIDE + kb + tq    ]);
                uint32_t b1 = __float_as_uint(Bb[nrow * A_STRIDE + kb + tq + 4]);
#pragma unroll
                for (int mt = 0; mt < 4; mt++)
                    mma_tf32(acc[g][mt], afr[mt][0], afr[mt][1], afr[mt][2], afr[mt][3], b0, b1);
            }
        }
        __syncthreads();
    }

    // ---- fused epilogue ----
    const int nn = n0 + wn * 8 + tq * 2;         // within-gate col (even)
    const float* xr = g_xg + (size_t)t * BATCH * G4;
#pragma unroll
    for (int mt = 0; mt < 4; mt++) {
#pragma unroll
        for (int half = 0; half < 2; half++) {   // c0,c1 (row) / c2,c3 (row+8)
            int m = m0 + wm * 64 + mt * 16 + gq + half * 8;
            size_t xrow = (size_t)m * G4;
            float2 xi = *(const float2*)&xr[xrow + 0 * HID + nn];
            float2 xf = *(const float2*)&xr[xrow + 1 * HID + nn];
            float2 xg2 = *(const float2*)&xr[xrow + 2 * HID + nn];
            float2 xo = *(const float2*)&xr[xrow + 3 * HID + nn];
            size_t hidx = (size_t)m * HID + nn;
            float2 cold = *(const float2*)&g_c[hidx];

            float2 hv, cv;
#pragma unroll
            for (int e = 0; e < 2; e++) {
                float gi = acc[0][mt][half * 2 + e] + (e ? xi.y : xi.x);
                float gf = acc[1][mt][half * 2 + e] + (e ? xf.y : xf.x);
                float gg = acc[2][mt][half * 2 + e] + (e ? xg2.y : xg2.x);
                float go = acc[3][mt][half * 2 + e] + (e ? xo.y : xo.x);
                float i_ = 1.f / (1.f + expf(-gi));
                float f_ = 1.f / (1.f + expf(-gf));
                float g_ = tanhf(gg);
                float o_ = 1.f / (1.f + expf(-go));
                float cn = f_ * (e ? cold.y : cold.x) + i_ * g_;
                float hn = o_ * tanhf(cn);
                if (e) { cv.y = cn; hv.y = hn; } else { cv.x = cn; hv.x = hn; }
            }
            *(float2*)&g_c[hidx]  = cv;
            *(float2*)&hout[hidx] = hv;
        }
    }
}

// ---------------- out proj + log_softmax ----------------
__global__ void out_logsoftmax(const float* __restrict__ W,
                               const float* __restrict__ bias,
                               float* __restrict__ out) {
    __shared__ float As[16][32 + 1];
    __shared__ float Bs[16][128];
    __shared__ float Ls[32][128 + 1];
    int tid = threadIdx.x;
    int tx = tid & 31, ty = tid >> 5;
    int bm = blockIdx.x * 32;
    float acc[4][4] = {};
    for (int k0 = 0; k0 < HID; k0 += 16) {
#pragma unroll
        for (int i = 0; i < 2; i++) {
            int idx = tid + i * 256;
            int r = idx >> 4, c = idx & 15;
            As[c][r] = g_hs[(size_t)(bm + r) * HID + k0 + c];
        }
#pragma unroll
        for (int i = 0; i < 8; i++) {
            int idx = tid + i * 256;
            int r = idx >> 7, c = idx & 127;
            Bs[r][c] = W[(size_t)(k0 + r) * VOCAB + c];
        }
        __syncthreads();
#pragma unroll
        for (int kk = 0; kk < 16; kk++) {
            float a0 = As[kk][ty * 4 + 0], a1 = As[kk][ty * 4 + 1];
            float a2 = As[kk][ty * 4 + 2], a3 = As[kk][ty * 4 + 3];
            float b0 = Bs[kk][tx * 4 + 0], b1 = Bs[kk][tx * 4 + 1];
            float b2 = Bs[kk][tx * 4 + 2], b3 = Bs[kk][tx * 4 + 3];
            acc[0][0] += a0 * b0; acc[0][1] += a0 * b1; acc[0][2] += a0 * b2; acc[0][3] += a0 * b3;
            acc[1][0] += a1 * b0; acc[1][1] += a1 * b1; acc[1][2] += a1 * b2; acc[1][3] += a1 * b3;
            acc[2][0] += a2 * b0; acc[2][1] += a2 * b1; acc[2][2] += a2 * b2; acc[2][3] += a2 * b3;
            acc[3][0] += a3 * b0; acc[3][1] += a3 * b1; acc[3][2] += a3 * b2; acc[3][3] += a3 * b3;
        }
        __syncthreads();
    }
#pragma unroll
    for (int r = 0; r < 4; r++)
#pragma unroll
        for (int c = 0; c < 4; c++)
            Ls[ty * 4 + r][tx * 4 + c] = acc[r][c] + bias[tx * 4 + c];
    __syncthreads();

    int warp = tid >> 5, lane = tid & 31;
#pragma unroll
    for (int r = 0; r < 4; r++) {
        int row = warp * 4 + r;
        float v0 = Ls[row][lane], v1 = Ls[row][lane + 32];
        float v2 = Ls[row][lane + 64], v3 = Ls[row][lane + 96];
        float mx = fmaxf(fmaxf(v0, v1), fmaxf(v2, v3));
#pragma unroll
        for (int off = 16; off; off >>= 1) mx = fmaxf(mx, __shfl_xor_sync(0xffffffffu, mx, off));
        float s = expf(v0 - mx) + expf(v1 - mx) + expf(v2 - mx) + expf(v3 - mx);
#pragma unroll
        for (int off = 16; off; off >>= 1) s += __shfl_xor_sync(0xffffffffu, s, off);
        float lse = mx + logf(s);
        size_t base = (size_t)(bm + row) * VOCAB;
        out[base + lane]      = v0 - lse;
        out[base + lane + 32] = v1 - lse;
        out[base + lane + 64] = v2 - lse;
        out[base + lane + 96] = v3 - lse;
    }
}

// ---------------- launch ----------------
extern "C" void kernel_launch(void* const* d_in, const int* in_sizes, int n_in,
                              void* d_out, int out_size) {
    const float* inp = (const float*)d_in[0];
    const float* img = (const float*)d_in[1];
    const float* c1w = (const float*)d_in[2];
    const float* c1b = (const float*)d_in[3];
    const float* c2w = (const float*)d_in[4];
    const float* c2b = (const float*)d_in[5];
    const float* fw  = (const float*)d_in[6];
    const float* fb  = (const float*)d_in[7];
    const float* xhw = (const float*)d_in[8];
    const float* xhb = (const float*)d_in[9];
    const float* hhw = (const float*)d_in[10];
    const float* hhb = (const float*)d_in[11];
    const float* ow  = (const float*)d_in[12];
    const float* ob  = (const float*)d_in[13];
    float* out = (float*)d_out;

    cudaFuncSetAttribute(lstm_step_mma, cudaFuncAttributeMaxDynamicSharedMemorySize, LSTM_SMEM);

    zero_hc<<<(BATCH * HID) / 256, 256>>>();
    transpose_hh<<<dim3(G4 / 32, HID / 32), dim3(32, 8)>>>(hhw);
    conv1_pool<<<(BATCH * 8 * 32 * 32) / 256, 256>>>(img, c1w, c1b);
    conv2_pool<<<(BATCH * 16 * 15 * 15) / 256, 256>>>(c2w, c2b);
    imgfc_gemm<<<dim3(HID / 64, BATCH / 64), 256>>>(fw, fb);
    xg_gemm<<<dim3(G4 / 64, (T_LEN * BATCH) / 64), 256>>>(inp, xhw, xhb, hhb);

    for (int t = 0; t < T_LEN; t++)
        lstm_step_mma<<<dim3(HID / 32, BATCH / 128), 256, LSTM_SMEM>>>(t);

    out_logsoftmax<<<(T_LEN * BATCH) / 32, 256>>>(ow, ob, out);
}

// round 4
// speedup vs baseline: 1.6297x; 1.0058x over previous
#include <cuda_runtime.h>
#include <math.h>
#include <stdint.h>

#define T_LEN   64
#define BATCH   1024
#define VOCAB   128
#define HID     512
#define G4      2048
#define IMGFEAT 3600

// ---------------- helpers ----------------
__device__ __forceinline__ void cp16(uint32_t dst, const float* src) {
    size_t g = __cvta_generic_to_global((void*)src);
    asm volatile("cp.async.cg.shared.global [%0], [%1], 16;" :: "r"(dst), "l"(g));
}
#define CP_COMMIT() asm volatile("cp.async.commit_group;" ::: "memory")
#define CP_WAIT(n)  asm volatile("cp.async.wait_group %0;" :: "n"(n) : "memory")

__device__ __forceinline__ uint32_t smem_u32(const void* p) {
    uint32_t a;
    asm("{ .reg .u64 t; cvta.to.shared.u64 t, %1; cvt.u32.u64 %0, t; }" : "=r"(a) : "l"(p));
    return a;
}

// m16n8k8 tf32 mma (row.col), fp32 accumulate
__device__ __forceinline__ void mma_tf32(float c[4],
                                         uint32_t a0, uint32_t a1, uint32_t a2, uint32_t a3,
                                         uint32_t b0, uint32_t b1) {
    asm volatile(
        "mma.sync.aligned.m16n8k8.row.col.f32.tf32.tf32.f32 "
        "{%0,%1,%2,%3}, {%4,%5,%6,%7}, {%8,%9}, {%0,%1,%2,%3};"
        : "+f"(c[0]), "+f"(c[1]), "+f"(c[2]), "+f"(c[3])
        : "r"(a0), "r"(a1), "r"(a2), "r"(a3), "r"(b0), "r"(b1));
}

// ---------------- scratch ----------------
__device__ float g_a1[BATCH * 8 * 32 * 32];
__device__ float g_a2[BATCH * 16 * 15 * 15];
__device__ float g_e [BATCH * HID];
__device__ float g_wt[(size_t)G4 * HID];             // hh_w transposed: [2048,512] K-major
__device__ float g_xg[(size_t)T_LEN * BATCH * G4];   // xh proj + xh_b + hh_b (+ img4 at t=0)
__device__ float g_hs[(size_t)T_LEN * BATCH * HID];  // h chain / outputs
__device__ unsigned g_bar;                           // grid barrier counter

// ---------------- init ----------------
__global__ void zero_bar() { g_bar = 0; }

// ---------------- transpose hh_w [512,2048] -> g_wt [2048,512] ----------------
__global__ void transpose_hh(const float* __restrict__ W) {
    __shared__ float ts[32][33];
    int bx = blockIdx.x * 32;
    int by = blockIdx.y * 32;
    int x = threadIdx.x, y = threadIdx.y;
#pragma unroll
    for (int i = 0; i < 32; i += 8)
        ts[y + i][x] = W[(size_t)(by + y + i) * G4 + bx + x];
    __syncthreads();
#pragma unroll
    for (int i = 0; i < 32; i += 8)
        g_wt[(size_t)(bx + y + i) * HID + by + x] = ts[x][y + i];
}

// ---------------- conv1 (1->8,3x3,pad1)+relu+pool ----------------
__global__ void conv1_pool(const float* __restrict__ img,
                           const float* __restrict__ w,
                           const float* __restrict__ b) {
    int idx = blockIdx.x * blockDim.x + threadIdx.x;
    if (idx >= BATCH * 8 * 32 * 32) return;
    int px = idx & 31;
    int py = (idx >> 5) & 31;
    int oc = (idx >> 10) & 7;
    int bb = idx >> 13;
    const float* im = img + (size_t)bb * 64 * 64;
    const float* wk = w + oc * 9;
    float bias = b[oc];
    float m = -INFINITY;
#pragma unroll
    for (int dy = 0; dy < 2; dy++) {
#pragma unroll
        for (int dx = 0; dx < 2; dx++) {
            int y = py * 2 + dy, x = px * 2 + dx;
            float acc = bias;
#pragma unroll
            for (int ky = 0; ky < 3; ky++) {
                int iy = y + ky - 1;
                if ((unsigned)iy < 64u) {
#pragma unroll
                    for (int kx = 0; kx < 3; kx++) {
                        int ix = x + kx - 1;
                        if ((unsigned)ix < 64u)
                            acc += im[iy * 64 + ix] * wk[ky * 3 + kx];
                    }
                }
            }
            m = fmaxf(m, fmaxf(acc, 0.f));
        }
    }
    g_a1[idx] = m;
}

// ---------------- conv2 (8->16,5x5,pad1)+relu+pool ----------------
__global__ void conv2_pool(const float* __restrict__ w,
                           const float* __restrict__ b) {
    __shared__ float ws[16 * 8 * 25];
    for (int i = threadIdx.x; i < 16 * 8 * 25; i += blockDim.x) ws[i] = w[i];
    __syncthreads();
    int idx = blockIdx.x * blockDim.x + threadIdx.x;
    if (idx >= BATCH * 16 * 15 * 15) return;
    int px = idx % 15;
    int t  = idx / 15;
    int py = t % 15; t /= 15;
    int oc = t & 15;
    int bb = t >> 4;
    const float* a1b = g_a1 + (size_t)bb * 8 * 32 * 32;
    float bias = b[oc];
    float m = -INFINITY;
#pragma unroll
    for (int dy = 0; dy < 2; dy++) {
#pragma unroll
        for (int dx = 0; dx < 2; dx++) {
            int oy = py * 2 + dy, ox = px * 2 + dx;
            float acc = bias;
            for (int ic = 0; ic < 8; ic++) {
                const float* wp = ws + (oc * 8 + ic) * 25;
                const float* ap = a1b + ic * 1024;
#pragma unroll
                for (int ky = 0; ky < 5; ky++) {
                    int iy = oy + ky - 1;
                    if ((unsigned)iy < 32u) {
#pragma unroll
                        for (int kx = 0; kx < 5; kx++) {
                            int ix = ox + kx - 1;
                            if ((unsigned)ix < 32u)
                                acc += ap[iy * 32 + ix] * wp[ky * 5 + kx];
                        }
                    }
                }
            }
            m = fmaxf(m, fmaxf(acc, 0.f));
        }
    }
    g_a2[idx] = m;
}

// ---------------- imgfc: e = relu(a2 @ W + b) ----------------
__global__ void imgfc_gemm(const float* __restrict__ W,
                           const float* __restrict__ bias) {
    __shared__ float As[16][64 + 1];
    __shared__ float Bs[16][64];
    const int K = IMGFEAT, N = HID;
    int tid = threadIdx.x;
    int tx = tid & 15, ty = tid >> 4;
    int bm = blockIdx.y * 64, bn = blockIdx.x * 64;
    float acc[4][4] = {};
    for (int k0 = 0; k0 < K; k0 += 16) {
#pragma unroll
        for (int i = 0; i < 4; i++) {
            int idx = tid + i * 256;
            int r = idx >> 4, c = idx & 15;
            As[c][r] = g_a2[(size_t)(bm + r) * K + k0 + c];
        }
#pragma unroll
        for (int i = 0; i < 4; i++) {
            int idx = tid + i * 256;
            int r = idx >> 6, c = idx & 63;
            Bs[r][c] = W[(size_t)(k0 + r) * N + bn + c];
        }
        __syncthreads();
#pragma unroll
        for (int kk = 0; kk < 16; kk++) {
            float a0 = As[kk][ty * 4 + 0], a1 = As[kk][ty * 4 + 1];
            float a2 = As[kk][ty * 4 + 2], a3 = As[kk][ty * 4 + 3];
            float b0 = Bs[kk][tx * 4 + 0], b1 = Bs[kk][tx * 4 + 1];
            float b2 = Bs[kk][tx * 4 + 2], b3 = Bs[kk][tx * 4 + 3];
            acc[0][0] += a0 * b0; acc[0][1] += a0 * b1; acc[0][2] += a0 * b2; acc[0][3] += a0 * b3;
            acc[1][0] += a1 * b0; acc[1][1] += a1 * b1; acc[1][2] += a1 * b2; acc[1][3] += a1 * b3;
            acc[2][0] += a2 * b0; acc[2][1] += a2 * b1; acc[2][2] += a2 * b2; acc[2][3] += a2 * b3;
            acc[3][0] += a3 * b0; acc[3][1] += a3 * b1; acc[3][2] += a3 * b2; acc[3][3] += a3 * b3;
        }
        __syncthreads();
    }
#pragma unroll
    for (int r = 0; r < 4; r++) {
        int m = bm + ty * 4 + r;
#pragma unroll
        for (int c = 0; c < 4; c++) {
            int n = bn + tx * 4 + c;
            float v = acc[r][c] + bias[n];
            g_e[(size_t)m * HID + n] = fmaxf(v, 0.f);
        }
    }
}

// ---------------- xg = inp @ xh_w + xh_b + hh_b (+ img4 on t==0 rows) ----------------
__global__ void xg_gemm(const float* __restrict__ A,
                        const float* __restrict__ W,
                        const float* __restrict__ bias,
                        const float* __restrict__ hhb) {
    __shared__ float As[16][64 + 1];
    __shared__ float Bs[16][64];
    const int K = VOCAB, N = G4;
    int tid = threadIdx.x;
    int tx = tid & 15, ty = tid >> 4;
    int bm = blockIdx.y * 64, bn = blockIdx.x * 64;
    float acc[4][4] = {};
    for (int k0 = 0; k0 < K; k0 += 16) {
#pragma unroll
        for (int i = 0; i < 4; i++) {
            int idx = tid + i * 256;
            int r = idx >> 4, c = idx & 15;
            As[c][r] = A[(size_t)(bm + r) * K + k0 + c];
        }
#pragma unroll
        for (int i = 0; i < 4; i++) {
            int idx = tid + i * 256;
            int r = idx >> 6, c = idx & 63;
            Bs[r][c] = W[(size_t)(k0 + r) * N + bn + c];
        }
        __syncthreads();
#pragma unroll
        for (int kk = 0; kk < 16; kk++) {
            float a0 = As[kk][ty * 4 + 0], a1 = As[kk][ty * 4 + 1];
            float a2 = As[kk][ty * 4 + 2], a3 = As[kk][ty * 4 + 3];
            float b0 = Bs[kk][tx * 4 + 0], b1 = Bs[kk][tx * 4 + 1];
            float b2 = Bs[kk][tx * 4 + 2], b3 = Bs[kk][tx * 4 + 3];
            acc[0][0] += a0 * b0; acc[0][1] += a0 * b1; acc[0][2] += a0 * b2; acc[0][3] += a0 * b3;
            acc[1][0] += a1 * b0; acc[1][1] += a1 * b1; acc[1][2] += a1 * b2; acc[1][3] += a1 * b3;
            acc[2][0] += a2 * b0; acc[2][1] += a2 * b1; acc[2][2] += a2 * b2; acc[2][3] += a2 * b3;
            acc[3][0] += a3 * b0; acc[3][1] += a3 * b1; acc[3][2] += a3 * b2; acc[3][3] += a3 * b3;
        }
        __syncthreads();
    }
#pragma unroll
    for (int r = 0; r < 4; r++) {
        int m = bm + ty * 4 + r;
#pragma unroll
        for (int c = 0; c < 4; c++) {
            int n = bn + tx * 4 + c;
            float v = acc[r][c] + bias[n] + hhb[n];
            if (m < BATCH) v += g_e[(size_t)m * HID + (n & (HID - 1))];
            g_xg[(size_t)m * N + n] = v;
        }
    }
}

// ---------------- persistent LSTM: all 64 steps in one kernel ----------------
// Grid = 128 CTAs (1/SM, co-resident) x 256 threads.
// CTA tile: 256 rows (mtile = blk>>5) x 16 gate-cols (nslice = blk&31), all 4 gates.
// B slice (4g x 16n x 512k fp32, stride 516) resident in SMEM for all steps.
// Cell state c lives in registers for all steps.
#define B_STRIDE   516
#define BSM_FLOATS (64 * B_STRIDE)               // 33024
#define A_STRIDE   36
#define ABUF_FLOATS (256 * A_STRIDE)             // 9216
#define LSTM_SMEM  ((BSM_FLOATS + 2 * ABUF_FLOATS) * 4)   // 205824 B

__global__ void __launch_bounds__(256, 1)
lstm_persistent() {
    extern __shared__ float sm[];
    float* Bsm = sm;
    float* Abuf = sm + BSM_FLOATS;
    const uint32_t abase = smem_u32(Abuf);
    const int tid = threadIdx.x, lane = tid & 31, wid = tid >> 5;
    const int wm = wid & 3, wn = wid >> 2;       // 4 m-groups of 64 rows, 2 n-groups of 8 cols
    const int gq = lane >> 2, tq = lane & 3;
    const int blk = blockIdx.x;
    const int n0 = (blk & 31) * 16;
    const int m0 = (blk >> 5) * 256;
    const int NCTA = 128;

    // ---- load resident B slice (once) ----
    for (int i = tid; i < 64 * 128; i += 256) {  // 64 rows x 128 float4
        int row = i >> 7, c4 = i & 127;
        int g = row >> 4, n = row & 15;
        *(float4*)&Bsm[row * B_STRIDE + c4 * 4] =
            *(const float4*)&g_wt[(size_t)(g * HID + n0 + n) * HID + c4 * 4];
    }

    float creg[4][2][2];                          // cell state, registers for all steps
#pragma unroll
    for (int mt = 0; mt < 4; mt++)
#pragma unroll
        for (int h = 0; h < 2; h++) creg[mt][h][0] = creg[mt][h][1] = 0.f;

    __syncthreads();

    const int nn = n0 + wn * 8 + tq * 2;          // within-gate col (even pair)
    unsigned bar_target = 0;

    for (int t = 0; t < T_LEN; t++) {
        float acc[4][4][4];                       // [gate][mtile][creg]
#pragma unroll
        for (int g = 0; g < 4; g++)
#pragma unroll
            for (int mt = 0; mt < 4; mt++)
#pragma unroll
                for (int j = 0; j < 4; j++) acc[g][mt][j] = 0.f;

        if (t > 0) {
            const float* hin = g_hs + (size_t)(t - 1) * BATCH * HID;
            // chunk 0
            {
#pragma unroll
                for (int j = 0; j < 8; j++) {     // 2048 float4 / 256 threads
                    int idx = tid + j * 256;
                    int r = idx >> 3, c4 = idx & 7;
                    cp16(abase + r * (A_STRIDE * 4) + c4 * 16,
                         hin + (size_t)(m0 + r) * HID + c4 * 4);
                }
                CP_COMMIT();
            }
            for (int i = 0; i < 16; i++) {
                if (i + 1 < 16) {
                    const int k0 = (i + 1) * 32;
                    const uint32_t dst = abase + ((i + 1) & 1) * (ABUF_FLOATS * 4);
#pragma unroll
                    for (int j = 0; j < 8; j++) {
                        int idx = tid + j * 256;
                        int r = idx >> 3, c4 = idx & 7;
                        cp16(dst + r * (A_STRIDE * 4) + c4 * 16,
                             hin + (size_t)(m0 + r) * HID + k0 + c4 * 4);
                    }
                    CP_COMMIT();
                    CP_WAIT(1);
                } else {
                    CP_WAIT(0);
                }
                __syncthreads();

                const float* Ab = Abuf + (i & 1) * ABUF_FLOATS;
                const int kabs = i * 32;
#pragma unroll
                for (int ks = 0; ks < 4; ks++) {
                    const int kb = ks * 8;
                    uint32_t afr[4][4];
#pragma unroll
                    for (int mt = 0; mt < 4; mt++) {
                        int r0 = wm * 64 + mt * 16 + gq;
                        afr[mt][0] = __float_as_uint(Ab[(r0    ) * A_STRIDE + kb + tq    ]);
                        afr[mt][1] = __float_as_uint(Ab[(r0 + 8) * A_STRIDE + kb + tq    ]);
                        afr[mt][2] = __float_as_uint(Ab[(r0    ) * A_STRIDE + kb + tq + 4]);
                        afr[mt][3] = __float_as_uint(Ab[(r0 + 8) * A_STRIDE + kb + tq + 4]);
                    }
#pragma unroll
                    for (int g = 0; g < 4; g++) {
                        int nrow = g * 16 + wn * 8 + gq;
                        uint32_t b0 = __float_as_uint(Bsm[nrow * B_STRIDE + kabs + kb + tq    ]);
                        uint32_t b1 = __float_as_uint(Bsm[nrow * B_STRIDE + kabs + kb + tq + 4]);
#pragma unroll
                        for (int mt = 0; mt < 4; mt++)
                            mma_tf32(acc[g][mt], afr[mt][0], afr[mt][1], afr[mt][2], afr[mt][3], b0, b1);
                    }
                }
                __syncthreads();
            }
        }

        // ---- fused epilogue (c in registers) ----
        const float* xr = g_xg + (size_t)t * BATCH * G4;
        float* hout = g_hs + (size_t)t * BATCH * HID;
#pragma unroll
        for (int mt = 0; mt < 4; mt++) {
#pragma unroll
            for (int half = 0; half < 2; half++) {
                int m = m0 + wm * 64 + mt * 16 + gq + half * 8;
                size_t xrow = (size_t)m * G4;
                float2 xi  = *(const float2*)&xr[xrow + 0 * HID + nn];
                float2 xf  = *(const float2*)&xr[xrow + 1 * HID + nn];
                float2 xg2 = *(const float2*)&xr[xrow + 2 * HID + nn];
                float2 xo  = *(const float2*)&xr[xrow + 3 * HID + nn];
                float2 hv;
#pragma unroll
                for (int e = 0; e < 2; e++) {
                    float gi = acc[0][mt][half * 2 + e] + (e ? xi.y : xi.x);
                    float gf = acc[1][mt][half * 2 + e] + (e ? xf.y : xf.x);
                    float gg = acc[2][mt][half * 2 + e] + (e ? xg2.y : xg2.x);
                    float go = acc[3][mt][half * 2 + e] + (e ? xo.y : xo.x);
                    float i_ = 1.f / (1.f + expf(-gi));
                    float f_ = 1.f / (1.f + expf(-gf));
                    float g_ = tanhf(gg);
                    float o_ = 1.f / (1.f + expf(-go));
                    float cn = f_ * creg[mt][half][e] + i_ * g_;
                    creg[mt][half][e] = cn;
                    float hn = o_ * tanhf(cn);
                    if (e) hv.y = hn; else hv.x = hn;
                }
                *(float2*)&hout[(size_t)m * HID + nn] = hv;
            }
        }

        // ---- grid barrier (all h[t] visible before anyone reads at t+1) ----
        if (t + 1 < T_LEN) {
            bar_target += NCTA;
            __syncthreads();
            if (tid == 0) {
                __threadfence();
                atomicAdd(&g_bar, 1u);
                while (*(volatile unsigned*)&g_bar < bar_target) { }
                __threadfence();
            }
            __syncthreads();
        }
    }
}

// ---------------- out proj + log_softmax ----------------
__global__ void out_logsoftmax(const float* __restrict__ W,
                               const float* __restrict__ bias,
                               float* __restrict__ out) {
    __shared__ float As[16][32 + 1];
    __shared__ float Bs[16][128];
    __shared__ float Ls[32][128 + 1];
    int tid = threadIdx.x;
    int tx = tid & 31, ty = tid >> 5;
    int bm = blockIdx.x * 32;
    float acc[4][4] = {};
    for (int k0 = 0; k0 < HID; k0 += 16) {
#pragma unroll
        for (int i = 0; i < 2; i++) {
            int idx = tid + i * 256;
            int r = idx >> 4, c = idx & 15;
            As[c][r] = g_hs[(size_t)(bm + r) * HID + k0 + c];
        }
#pragma unroll
        for (int i = 0; i < 8; i++) {
            int idx = tid + i * 256;
            int r = idx >> 7, c = idx & 127;
            Bs[r][c] = W[(size_t)(k0 + r) * VOCAB + c];
        }
        __syncthreads();
#pragma unroll
        for (int kk = 0; kk < 16; kk++) {
            float a0 = As[kk][ty * 4 + 0], a1 = As[kk][ty * 4 + 1];
            float a2 = As[kk][ty * 4 + 2], a3 = As[kk][ty * 4 + 3];
            float b0 = Bs[kk][tx * 4 + 0], b1 = Bs[kk][tx * 4 + 1];
            float b2 = Bs[kk][tx * 4 + 2], b3 = Bs[kk][tx * 4 + 3];
            acc[0][0] += a0 * b0; acc[0][1] += a0 * b1; acc[0][2] += a0 * b2; acc[0][3] += a0 * b3;
            acc[1][0] += a1 * b0; acc[1][1] += a1 * b1; acc[1][2] += a1 * b2; acc[1][3] += a1 * b3;
            acc[2][0] += a2 * b0; acc[2][1] += a2 * b1; acc[2][2] += a2 * b2; acc[2][3] += a2 * b3;
            acc[3][0] += a3 * b0; acc[3][1] += a3 * b1; acc[3][2] += a3 * b2; acc[3][3] += a3 * b3;
        }
        __syncthreads();
    }
#pragma unroll
    for (int r = 0; r < 4; r++)
#pragma unroll
        for (int c = 0; c < 4; c++)
            Ls[ty * 4 + r][tx * 4 + c] = acc[r][c] + bias[tx * 4 + c];
    __syncthreads();

    int warp = tid >> 5, lane = tid & 31;
#pragma unroll
    for (int r = 0; r < 4; r++) {
        int row = warp * 4 + r;
        float v0 = Ls[row][lane], v1 = Ls[row][lane + 32];
        float v2 = Ls[row][lane + 64], v3 = Ls[row][lane + 96];
        float mx = fmaxf(fmaxf(v0, v1), fmaxf(v2, v3));
#pragma unroll
        for (int off = 16; off; off >>= 1) mx = fmaxf(mx, __shfl_xor_sync(0xffffffffu, mx, off));
        float s = expf(v0 - mx) + expf(v1 - mx) + expf(v2 - mx) + expf(v3 - mx);
#pragma unroll
        for (int off = 16; off; off >>= 1) s += __shfl_xor_sync(0xffffffffu, s, off);
        float lse = mx + logf(s);
        size_t base = (size_t)(bm + row) * VOCAB;
        out[base + lane]      = v0 - lse;
        out[base + lane + 32] = v1 - lse;
        out[base + lane + 64] = v2 - lse;
        out[base + lane + 96] = v3 - lse;
    }
}

// ---------------- launch ----------------
extern "C" void kernel_launch(void* const* d_in, const int* in_sizes, int n_in,
                              void* d_out, int out_size) {
    const float* inp = (const float*)d_in[0];
    const float* img = (const float*)d_in[1];
    const float* c1w = (const float*)d_in[2];
    const float* c1b = (const float*)d_in[3];
    const float* c2w = (const float*)d_in[4];
    const float* c2b = (const float*)d_in[5];
    const float* fw  = (const float*)d_in[6];
    const float* fb  = (const float*)d_in[7];
    const float* xhw = (const float*)d_in[8];
    const float* xhb = (const float*)d_in[9];
    const float* hhw = (const float*)d_in[10];
    const float* hhb = (const float*)d_in[11];
    const float* ow  = (const float*)d_in[12];
    const float* ob  = (const float*)d_in[13];
    float* out = (float*)d_out;

    cudaFuncSetAttribute(lstm_persistent, cudaFuncAttributeMaxDynamicSharedMemorySize, LSTM_SMEM);

    zero_bar<<<1, 1>>>();
    transpose_hh<<<dim3(G4 / 32, HID / 32), dim3(32, 8)>>>(hhw);
    conv1_pool<<<(BATCH * 8 * 32 * 32) / 256, 256>>>(img, c1w, c1b);
    conv2_pool<<<(BATCH * 16 * 15 * 15) / 256, 256>>>(c2w, c2b);
    imgfc_gemm<<<dim3(HID / 64, BATCH / 64), 256>>>(fw, fb);
    xg_gemm<<<dim3(G4 / 64, (T_LEN * BATCH) / 64), 256>>>(inp, xhw, xhb, hhb);

    lstm_persistent<<<128, 256, LSTM_SMEM>>>();

    out_logsoftmax<<<(T_LEN * BATCH) / 32, 256>>>(ow, ob, out);
}

// round 5
// speedup vs baseline: 2.4860x; 1.5254x over previous
#include <cuda_runtime.h>
#include <cuda_bf16.h>
#include <math.h>
#include <stdint.h>

#define T_LEN   64
#define BATCH   1024
#define VOCAB   128
#define HID     512
#define G4      2048
#define IMGFEAT 3600

// ---------------- helpers ----------------
__device__ __forceinline__ void cp16(uint32_t dst, const void* src) {
    size_t g = __cvta_generic_to_global(src);
    asm volatile("cp.async.cg.shared.global [%0], [%1], 16;" :: "r"(dst), "l"(g));
}
#define CP_COMMIT() asm volatile("cp.async.commit_group;" ::: "memory")
#define CP_WAIT(n)  asm volatile("cp.async.wait_group %0;" :: "n"(n) : "memory")

__device__ __forceinline__ uint32_t smem_u32(const void* p) {
    uint32_t a;
    asm("{ .reg .u64 t; cvta.to.shared.u64 t, %1; cvt.u32.u64 %0, t; }" : "=r"(a) : "l"(p));
    return a;
}

// m16n8k16 bf16 mma (row.col), fp32 accumulate
__device__ __forceinline__ void mma_bf16(float c[4],
                                         uint32_t a0, uint32_t a1, uint32_t a2, uint32_t a3,
                                         uint32_t b0, uint32_t b1) {
    asm volatile(
        "mma.sync.aligned.m16n8k16.row.col.f32.bf16.bf16.f32 "
        "{%0,%1,%2,%3}, {%4,%5,%6,%7}, {%8,%9}, {%0,%1,%2,%3};"
        : "+f"(c[0]), "+f"(c[1]), "+f"(c[2]), "+f"(c[3])
        : "r"(a0), "r"(a1), "r"(a2), "r"(a3), "r"(b0), "r"(b1));
}

// m16n8k8 tf32 mma (row.col), fp32 accumulate
__device__ __forceinline__ void mma_tf32(float c[4],
                                         uint32_t a0, uint32_t a1, uint32_t a2, uint32_t a3,
                                         uint32_t b0, uint32_t b1) {
    asm volatile(
        "mma.sync.aligned.m16n8k8.row.col.f32.tf32.tf32.f32 "
        "{%0,%1,%2,%3}, {%4,%5,%6,%7}, {%8,%9}, {%0,%1,%2,%3};"
        : "+f"(c[0]), "+f"(c[1]), "+f"(c[2]), "+f"(c[3])
        : "r"(a0), "r"(a1), "r"(a2), "r"(a3), "r"(b0), "r"(b1));
}

// ---------------- scratch ----------------
__device__ float g_a1[BATCH * 8 * 32 * 32];
__device__ float g_a2[BATCH * 16 * 15 * 15];
__device__ float g_e [BATCH * HID];
__device__ __nv_bfloat16 g_wt[(size_t)G4 * HID];    // hh_w^T  [2048,512] bf16
__device__ __nv_bfloat16 g_xt[(size_t)G4 * VOCAB];  // xh_w^T  [2048,128] bf16
__device__ float g_owt[VOCAB * HID];                // out_w^T [128,512] f32
__device__ __nv_bfloat16 g_xb[(size_t)T_LEN * BATCH * VOCAB];  // bf16 inp
__device__ float g_b4[G4];                          // xh_b + hh_b
__device__ __nv_bfloat16 g_hb0[BATCH * HID];        // h bf16 ping
__device__ __nv_bfloat16 g_hb1[BATCH * HID];        // h bf16 pong
__device__ float g_hs[(size_t)T_LEN * BATCH * HID]; // h fp32 (out proj input)
__device__ unsigned g_bar;

// ---------------- small kernels ----------------
__global__ void zero_bar() { g_bar = 0; }

__global__ void bias4(const float* __restrict__ xhb, const float* __restrict__ hhb) {
    int i = blockIdx.x * blockDim.x + threadIdx.x;
    if (i < G4) g_b4[i] = xhb[i] + hhb[i];
}

__global__ void cvt_inp(const float* __restrict__ inp) {
    int i = blockIdx.x * blockDim.x + threadIdx.x;   // over float2 pairs
    const float2* s = (const float2*)inp;
    __nv_bfloat162* d = (__nv_bfloat162*)g_xb;
    d[i] = __float22bfloat162_rn(s[i]);
}

// transpose src[K][N] (f32) -> dst[N][K] (bf16). grid (N/32, K/32), block (32,8)
__global__ void transpose_bf16(const float* __restrict__ src, __nv_bfloat16* __restrict__ dst,
                               int K, int N) {
    __shared__ float ts[32][33];
    int bn = blockIdx.x * 32, bk = blockIdx.y * 32;
    int x = threadIdx.x, y = threadIdx.y;
#pragma unroll
    for (int i = 0; i < 32; i += 8)
        ts[y + i][x] = src[(size_t)(bk + y + i) * N + bn + x];
    __syncthreads();
#pragma unroll
    for (int i = 0; i < 32; i += 8)
        dst[(size_t)(bn + y + i) * K + bk + x] = __float2bfloat16_rn(ts[x][y + i]);
}

// transpose src[K][N] (f32) -> dst[N][K] (f32)
__global__ void transpose_f32(const float* __restrict__ src, float* __restrict__ dst,
                              int K, int N) {
    __shared__ float ts[32][33];
    int bn = blockIdx.x * 32, bk = blockIdx.y * 32;
    int x = threadIdx.x, y = threadIdx.y;
#pragma unroll
    for (int i = 0; i < 32; i += 8)
        ts[y + i][x] = src[(size_t)(bk + y + i) * N + bn + x];
    __syncthreads();
#pragma unroll
    for (int i = 0; i < 32; i += 8)
        dst[(size_t)(bn + y + i) * K + bk + x] = ts[x][y + i];
}

// ---------------- conv1 (1->8,3x3,pad1)+relu+pool ----------------
__global__ void conv1_pool(const float* __restrict__ img,
                           const float* __restrict__ w,
                           const float* __restrict__ b) {
    int idx = blockIdx.x * blockDim.x + threadIdx.x;
    if (idx >= BATCH * 8 * 32 * 32) return;
    int px = idx & 31;
    int py = (idx >> 5) & 31;
    int oc = (idx >> 10) & 7;
    int bb = idx >> 13;
    const float* im = img + (size_t)bb * 64 * 64;
    const float* wk = w + oc * 9;
    float bias = b[oc];
    float m = -INFINITY;
#pragma unroll
    for (int dy = 0; dy < 2; dy++) {
#pragma unroll
        for (int dx = 0; dx < 2; dx++) {
            int y = py * 2 + dy, x = px * 2 + dx;
            float acc = bias;
#pragma unroll
            for (int ky = 0; ky < 3; ky++) {
                int iy = y + ky - 1;
                if ((unsigned)iy < 64u) {
#pragma unroll
                    for (int kx = 0; kx < 3; kx++) {
                        int ix = x + kx - 1;
                        if ((unsigned)ix < 64u)
                            acc += im[iy * 64 + ix] * wk[ky * 3 + kx];
                    }
                }
            }
            m = fmaxf(m, fmaxf(acc, 0.f));
        }
    }
    g_a1[idx] = m;
}

// ---------------- conv2 (8->16,5x5,pad1)+relu+pool ----------------
__global__ void conv2_pool(const float* __restrict__ w,
                           const float* __restrict__ b) {
    __shared__ float ws[16 * 8 * 25];
    for (int i = threadIdx.x; i < 16 * 8 * 25; i += blockDim.x) ws[i] = w[i];
    __syncthreads();
    int idx = blockIdx.x * blockDim.x + threadIdx.x;
    if (idx >= BATCH * 16 * 15 * 15) return;
    int px = idx % 15;
    int t  = idx / 15;
    int py = t % 15; t /= 15;
    int oc = t & 15;
    int bb = t >> 4;
    const float* a1b = g_a1 + (size_t)bb * 8 * 32 * 32;
    float bias = b[oc];
    float m = -INFINITY;
#pragma unroll
    for (int dy = 0; dy < 2; dy++) {
#pragma unroll
        for (int dx = 0; dx < 2; dx++) {
            int oy = py * 2 + dy, ox = px * 2 + dx;
            float acc = bias;
            for (int ic = 0; ic < 8; ic++) {
                const float* wp = ws + (oc * 8 + ic) * 25;
                const float* ap = a1b + ic * 1024;
#pragma unroll
                for (int ky = 0; ky < 5; ky++) {
                    int iy = oy + ky - 1;
                    if ((unsigned)iy < 32u) {
#pragma unroll
                        for (int kx = 0; kx < 5; kx++) {
                            int ix = ox + kx - 1;
                            if ((unsigned)ix < 32u)
                                acc += ap[iy * 32 + ix] * wp[ky * 5 + kx];
                        }
                    }
                }
            }
            m = fmaxf(m, fmaxf(acc, 0.f));
        }
    }
    g_a2[idx] = m;
}

// ---------------- imgfc: e = relu(a2 @ W + b) ----------------
__global__ void imgfc_gemm(const float* __restrict__ W,
                           const float* __restrict__ bias) {
    __shared__ float As[16][64 + 1];
    __shared__ float Bs[16][64];
    const int K = IMGFEAT, N = HID;
    int tid = threadIdx.x;
    int tx = tid & 15, ty = tid >> 4;
    int bm = blockIdx.y * 64, bn = blockIdx.x * 64;
    float acc[4][4] = {};
    for (int k0 = 0; k0 < K; k0 += 16) {
#pragma unroll
        for (int i = 0; i < 4; i++) {
            int idx = tid + i * 256;
            int r = idx >> 4, c = idx & 15;
            As[c][r] = g_a2[(size_t)(bm + r) * K + k0 + c];
        }
#pragma unroll
        for (int i = 0; i < 4; i++) {
            int idx = tid + i * 256;
            int r = idx >> 6, c = idx & 63;
            Bs[r][c] = W[(size_t)(k0 + r) * N + bn + c];
        }
        __syncthreads();
#pragma unroll
        for (int kk = 0; kk < 16; kk++) {
            float a0 = As[kk][ty * 4 + 0], a1 = As[kk][ty * 4 + 1];
            float a2 = As[kk][ty * 4 + 2], a3 = As[kk][ty * 4 + 3];
            float b0 = Bs[kk][tx * 4 + 0], b1 = Bs[kk][tx * 4 + 1];
            float b2 = Bs[kk][tx * 4 + 2], b3 = Bs[kk][tx * 4 + 3];
            acc[0][0] += a0 * b0; acc[0][1] += a0 * b1; acc[0][2] += a0 * b2; acc[0][3] += a0 * b3;
            acc[1][0] += a1 * b0; acc[1][1] += a1 * b1; acc[1][2] += a1 * b2; acc[1][3] += a1 * b3;
            acc[2][0] += a2 * b0; acc[2][1] += a2 * b1; acc[2][2] += a2 * b2; acc[2][3] += a2 * b3;
            acc[3][0] += a3 * b0; acc[3][1] += a3 * b1; acc[3][2] += a3 * b2; acc[3][3] += a3 * b3;
        }
        __syncthreads();
    }
#pragma unroll
    for (int r = 0; r < 4; r++) {
        int m = bm + ty * 4 + r;
#pragma unroll
        for (int c = 0; c < 4; c++) {
            int n = bn + tx * 4 + c;
            float v = acc[r][c] + bias[n];
            g_e[(size_t)m * HID + n] = fmaxf(v, 0.f);
        }
    }
}

// ---------------- persistent LSTM: x-proj + h-proj fused, bf16 mma ----------------
// Grid = 128 CTAs x 256 threads. CTA tile: 256 rows x 16 gate-cols (all 4 gates).
// Resident SMEM (bf16, u32-packed): Whh slice [64 rows x 512K], Wxh slice [64 x 128K].
// A (h_prev or x_t) double-buffered in 32-K chunks. Cell state in registers.
#define BHH_STRIDE 260                       // u32 per row (256 data + 4 pad)
#define BXH_STRIDE 68                        // u32 per row (64 data + 4 pad)
#define A_STRIDE_U 20                        // u32 per row (16 data + 4 pad)
#define BHH_BYTES  (64 * BHH_STRIDE * 4)     // 66560
#define BXH_BYTES  (64 * BXH_STRIDE * 4)     // 17408
#define ABUF_BYTES (256 * A_STRIDE_U * 4)    // 20480
#define LSTM_SMEM  (BHH_BYTES + BXH_BYTES + 2 * ABUF_BYTES)  // 124928

__global__ void __launch_bounds__(256, 1)
lstm_persistent() {
    extern __shared__ char sm[];
    uint32_t* Bhh = (uint32_t*)sm;
    uint32_t* Bxh = (uint32_t*)(sm + BHH_BYTES);
    char* Abuf = sm + BHH_BYTES + BXH_BYTES;
    const uint32_t abase = smem_u32(Abuf);
    const int tid = threadIdx.x, lane = tid & 31, wid = tid >> 5;
    const int wm = wid & 3, wn = wid >> 2;   // 4 m-groups of 64 rows, 2 n-groups of 8 cols
    const int gq = lane >> 2, tq = lane & 3;
    const int blk = blockIdx.x;
    const int n0 = (blk & 31) * 16;
    const int m0 = (blk >> 5) * 256;
    const int NCTA = 128;

    // ---- resident weight slices (once) ----
    for (int i = tid; i < 64 * 64; i += 256) {           // Whh: 64 rows x 64 uint4
        int row = i >> 6, c4 = i & 63;
        int g = row >> 4, n = row & 15;
        *(uint4*)((char*)Bhh + row * (BHH_STRIDE * 4) + c4 * 16) =
            *(const uint4*)((const char*)(g_wt + (size_t)(g * HID + n0 + n) * HID) + c4 * 16);
    }
    for (int i = tid; i < 64 * 16; i += 256) {           // Wxh: 64 rows x 16 uint4
        int row = i >> 4, c4 = i & 15;
        int g = row >> 4, n = row & 15;
        *(uint4*)((char*)Bxh + row * (BXH_STRIDE * 4) + c4 * 16) =
            *(const uint4*)((const char*)(g_xt + (size_t)(g * HID + n0 + n) * VOCAB) + c4 * 16);
    }

    float creg[4][2][2];
#pragma unroll
    for (int mt = 0; mt < 4; mt++)
#pragma unroll
        for (int h = 0; h < 2; h++) creg[mt][h][0] = creg[mt][h][1] = 0.f;

    __syncthreads();

    const int nn = n0 + wn * 8 + tq * 2;
    unsigned bar_target = 0;

    for (int t = 0; t < T_LEN; t++) {
        const __nv_bfloat16* hb_r = (t & 1) ? g_hb0 : g_hb1;   // written at t-1
        __nv_bfloat16*       hb_w = (t & 1) ? g_hb1 : g_hb0;
        const int nch = (t == 0) ? 4 : 20;                     // 16 h-chunks + 4 x-chunks

        float acc[4][4][4];
#pragma unroll
        for (int g = 0; g < 4; g++)
#pragma unroll
            for (int mt = 0; mt < 4; mt++)
#pragma unroll
                for (int j = 0; j < 4; j++) acc[g][mt][j] = 0.f;

        // chunk c: h-part if (t>0 && c<16), else x-part with kc = c - (t>0?16:0)
        auto load_chunk = [&](int c, int p) {
            const uint32_t dst = abase + (uint32_t)p * ABUF_BYTES;
            bool isx = (t == 0) || (c >= 16);
            int kc = isx ? (t == 0 ? c : c - 16) : c;
#pragma unroll
            for (int j = 0; j < 4; j++) {                      // 1024 x 16B / 256 thr
                int idx = tid + j * 256;
                int r = idx >> 2, c4 = idx & 3;
                const __nv_bfloat16* src = isx
                    ? g_xb + ((size_t)t * BATCH + m0 + r) * VOCAB + kc * 32 + c4 * 8
                    : hb_r + (size_t)(m0 + r) * HID + kc * 32 + c4 * 8;
                cp16(dst + r * (A_STRIDE_U * 4) + c4 * 16, src);
            }
            CP_COMMIT();
        };

        load_chunk(0, 0);
        for (int c = 0; c < nch; c++) {
            if (c + 1 < nch) { load_chunk(c + 1, (c + 1) & 1); CP_WAIT(1); }
            else             { CP_WAIT(0); }
            __syncthreads();

            bool isx = (t == 0) || (c >= 16);
            int kc = isx ? (t == 0 ? c : c - 16) : c;
            const uint32_t* Bb = isx ? Bxh : Bhh;
            const int bstride = isx ? BXH_STRIDE : BHH_STRIDE;
            const int kabs2 = kc * 16;
            const uint32_t* Apk = (const uint32_t*)(Abuf + (c & 1) * ABUF_BYTES);

#pragma unroll
            for (int ks = 0; ks < 2; ks++) {                   // two k16 halves of 32-chunk
                uint32_t afr[4][4];
#pragma unroll
                for (int mt = 0; mt < 4; mt++) {
                    int r0 = wm * 64 + mt * 16 + gq;
                    afr[mt][0] = Apk[(r0    ) * A_STRIDE_U + ks * 8 + tq    ];
                    afr[mt][1] = Apk[(r0 + 8) * A_STRIDE_U + ks * 8 + tq    ];
                    afr[mt][2] = Apk[(r0    ) * A_STRIDE_U + ks * 8 + tq + 4];
                    afr[mt][3] = Apk[(r0 + 8) * A_STRIDE_U + ks * 8 + tq + 4];
                }
#pragma unroll
                for (int g = 0; g < 4; g++) {
                    int nrow = g * 16 + wn * 8 + gq;
                    uint32_t b0 = Bb[nrow * bstride + kabs2 + ks * 8 + tq    ];
                    uint32_t b1 = Bb[nrow * bstride + kabs2 + ks * 8 + tq + 4];
#pragma unroll
                    for (int mt = 0; mt < 4; mt++)
                        mma_bf16(acc[g][mt], afr[mt][0], afr[mt][1], afr[mt][2], afr[mt][3], b0, b1);
                }
            }
            __syncthreads();
        }

        // ---- fused epilogue ----
        float2 b4i = *(const float2*)&g_b4[0 * HID + nn];
        float2 b4f = *(const float2*)&g_b4[1 * HID + nn];
        float2 b4g = *(const float2*)&g_b4[2 * HID + nn];
        float2 b4o = *(const float2*)&g_b4[3 * HID + nn];
        float* hs_t = g_hs + (size_t)t * BATCH * HID;
#pragma unroll
        for (int mt = 0; mt < 4; mt++) {
#pragma unroll
            for (int half = 0; half < 2; half++) {
                int m = m0 + wm * 64 + mt * 16 + gq + half * 8;
                float2 ev = make_float2(0.f, 0.f);
                if (t == 0) ev = *(const float2*)&g_e[(size_t)m * HID + nn];
                float2 hv;
#pragma unroll
                for (int e = 0; e < 2; e++) {
                    float ee = e ? ev.y : ev.x;
                    float gi = acc[0][mt][half * 2 + e] + (e ? b4i.y : b4i.x) + ee;
                    float gf = acc[1][mt][half * 2 + e] + (e ? b4f.y : b4f.x) + ee;
                    float gg = acc[2][mt][half * 2 + e] + (e ? b4g.y : b4g.x) + ee;
                    float go = acc[3][mt][half * 2 + e] + (e ? b4o.y : b4o.x) + ee;
                    float i_ = 1.f / (1.f + expf(-gi));
                    float f_ = 1.f / (1.f + expf(-gf));
                    float g_ = tanhf(gg);
                    float o_ = 1.f / (1.f + expf(-go));
                    float cn = f_ * creg[mt][half][e] + i_ * g_;
                    creg[mt][half][e] = cn;
                    float hn = o_ * tanhf(cn);
                    if (e) hv.y = hn; else hv.x = hn;
                }
                size_t hidx = (size_t)m * HID + nn;
                *(float2*)&hs_t[hidx] = hv;
                *(__nv_bfloat162*)&hb_w[hidx] = __float22bfloat162_rn(hv);
            }
        }

        // ---- grid barrier ----
        if (t + 1 < T_LEN) {
            bar_target += NCTA;
            __syncthreads();
            if (tid == 0) {
                __threadfence();
                atomicAdd(&g_bar, 1u);
                while (*(volatile unsigned*)&g_bar < bar_target) { }
                __threadfence();
            }
            __syncthreads();
        }
    }
}

// ---------------- out proj (tf32 mma) + fused log_softmax ----------------
// Grid 1024 CTAs x 256 threads: 64 rows x 128 cols per CTA, K=512.
#define O_AS 36                               // f32 stride A/B smem
#define O_ABUF (64 * O_AS)                    // 2304 f
#define O_BBUF (128 * O_AS)                   // 4608 f
#define O_LS   (64 * 132)                     // 8448 f
#define OUT_SMEM ((2 * O_ABUF + 2 * O_BBUF + O_LS) * 4)   // 89088 B

__global__ void __launch_bounds__(256, 1)
out_logsoftmax_tc(const float* __restrict__ bias, float* __restrict__ out) {
    extern __shared__ float smf[];
    float* As = smf;
    float* Bs = smf + 2 * O_ABUF;
    float* Ls = smf + 2 * O_ABUF + 2 * O_BBUF;
    const uint32_t a_u = smem_u32(As), b_u = smem_u32(Bs);
    const int tid = threadIdx.x, lane = tid & 31, wid = tid >> 5;
    const int wm = wid & 1, wn = wid >> 1;    // 2 m-groups x 4 n-groups
    const int gq = lane >> 2, tq = lane & 3;
    const int bm = blockIdx.x * 64;

    float acc[2][4][4] = {};                  // [mt][nt][4]

    auto load_chunk = [&](int k0, int p) {
#pragma unroll
        for (int j = 0; j < 2; j++) {         // A: 64 rows x 8 f4
            int idx = tid + j * 256;
            int r = idx >> 3, c4 = idx & 7;
            cp16(a_u + p * O_ABUF * 4 + r * (O_AS * 4) + c4 * 16,
                 g_hs + (size_t)(bm + r) * HID + k0 + c4 * 4);
        }
#pragma unroll
        for (int j = 0; j < 4; j++) {         // B: 128 rows x 8 f4
            int idx = tid + j * 256;
            int r = idx >> 3, c4 = idx & 7;
            cp16(b_u + p * O_BBUF * 4 + r * (O_AS * 4) + c4 * 16,
                 g_owt + (size_t)r * HID + k0 + c4 * 4);
        }
        CP_COMMIT();
    };

    load_chunk(0, 0);
    for (int c = 0; c < 16; c++) {
        if (c + 1 < 16) { load_chunk((c + 1) * 32, (c + 1) & 1); CP_WAIT(1); }
        else            { CP_WAIT(0); }
        __syncthreads();
        const float* Ab = As + (c & 1) * O_ABUF;
        const float* Bb = Bs + (c & 1) * O_BBUF;
#pragma unroll
        for (int ks = 0; ks < 4; ks++) {
            const int kb = ks * 8;
            uint32_t afr[2][4];
#pragma unroll
            for (int mt = 0; mt < 2; mt++) {
                int r0 = wm * 32 + mt * 16 + gq;
                afr[mt][0] = __float_as_uint(Ab[(r0    ) * O_AS + kb + tq    ]);
                afr[mt][1] = __float_as_uint(Ab[(r0 + 8) * O_AS + kb + tq    ]);
                afr[mt][2] = __float_as_uint(Ab[(r0    ) * O_AS + kb + tq + 4]);
                afr[mt][3] = __float_as_uint(Ab[(r0 + 8) * O_AS + kb + tq + 4]);
            }
#pragma unroll
            for (int nt = 0; nt < 4; nt++) {
                int nrow = wn * 32 + nt * 8 + gq;
                uint32_t b0 = __float_as_uint(Bb[nrow * O_AS + kb + tq    ]);
                uint32_t b1 = __float_as_uint(Bb[nrow * O_AS + kb + tq + 4]);
#pragma unroll
                for (int mt = 0; mt < 2; mt++)
                    mma_tf32(acc[mt][nt], afr[mt][0], afr[mt][1], afr[mt][2], afr[mt][3], b0, b1);
            }
        }
        __syncthreads();
    }

    // logits tile -> smem (with bias)
#pragma unroll
    for (int mt = 0; mt < 2; mt++)
#pragma unroll
        for (int nt = 0; nt < 4; nt++) {
            int row = wm * 32 + mt * 16 + gq;
            int col = wn * 32 + nt * 8 + tq * 2;
            float b0 = bias[col], b1 = bias[col + 1];
            Ls[(row    ) * 132 + col    ] = acc[mt][nt][0] + b0;
            Ls[(row    ) * 132 + col + 1] = acc[mt][nt][1] + b1;
            Ls[(row + 8) * 132 + col    ] = acc[mt][nt][2] + b0;
            Ls[(row + 8) * 132 + col + 1] = acc[mt][nt][3] + b1;
        }
    __syncthreads();

#pragma unroll
    for (int rr = 0; rr < 8; rr++) {
        int row = wid * 8 + rr;
        float v0 = Ls[row * 132 + lane], v1 = Ls[row * 132 + lane + 32];
        float v2 = Ls[row * 132 + lane + 64], v3 = Ls[row * 132 + lane + 96];
        float mx = fmaxf(fmaxf(v0, v1), fmaxf(v2, v3));
#pragma unroll
        for (int off = 16; off; off >>= 1) mx = fmaxf(mx, __shfl_xor_sync(0xffffffffu, mx, off));
        float s = expf(v0 - mx) + expf(v1 - mx) + expf(v2 - mx) + expf(v3 - mx);
#pragma unroll
        for (int off = 16; off; off >>= 1) s += __shfl_xor_sync(0xffffffffu, s, off);
        float lse = mx + logf(s);
        size_t base = (size_t)(bm + row) * VOCAB;
        out[base + lane]      = v0 - lse;
        out[base + lane + 32] = v1 - lse;
        out[base + lane + 64] = v2 - lse;
        out[base + lane + 96] = v3 - lse;
    }
}

// ---------------- launch ----------------
extern "C" void kernel_launch(void* const* d_in, const int* in_sizes, int n_in,
                              void* d_out, int out_size) {
    const float* inp = (const float*)d_in[0];
    const float* img = (const float*)d_in[1];
    const float* c1w = (const float*)d_in[2];
    const float* c1b = (const float*)d_in[3];
    const float* c2w = (const float*)d_in[4];
    const float* c2b = (const float*)d_in[5];
    const float* fw  = (const float*)d_in[6];
    const float* fb  = (const float*)d_in[7];
    const float* xhw = (const float*)d_in[8];
    const float* xhb = (const float*)d_in[9];
    const float* hhw = (const float*)d_in[10];
    const float* hhb = (const float*)d_in[11];
    const float* ow  = (const float*)d_in[12];
    const float* ob  = (const float*)d_in[13];
    float* out = (float*)d_out;

    cudaFuncSetAttribute(lstm_persistent, cudaFuncAttributeMaxDynamicSharedMemorySize, LSTM_SMEM);
    cudaFuncSetAttribute(out_logsoftmax_tc, cudaFuncAttributeMaxDynamicSharedMemorySize, OUT_SMEM);

    __nv_bfloat16* wt_p; cudaGetSymbolAddress((void**)&wt_p, g_wt);
    __nv_bfloat16* xt_p; cudaGetSymbolAddress((void**)&xt_p, g_xt);
    float* owt_p;        cudaGetSymbolAddress((void**)&owt_p, g_owt);

    zero_bar<<<1, 1>>>();
    bias4<<<G4 / 256, 256>>>(xhb, hhb);
    cvt_inp<<<(T_LEN * BATCH * VOCAB / 2) / 256, 256>>>(inp);
    transpose_bf16<<<dim3(G4 / 32, HID / 32), dim3(32, 8)>>>(hhw, wt_p, HID, G4);
    transpose_bf16<<<dim3(G4 / 32, VOCAB / 32), dim3(32, 8)>>>(xhw, xt_p, VOCAB, G4);
    transpose_f32<<<dim3(VOCAB / 32, HID / 32), dim3(32, 8)>>>(ow, owt_p, HID, VOCAB);
    conv1_pool<<<(BATCH * 8 * 32 * 32) / 256, 256>>>(img, c1w, c1b);
    conv2_pool<<<(BATCH * 16 * 15 * 15) / 256, 256>>>(c2w, c2b);
    imgfc_gemm<<<dim3(HID / 64, BATCH / 64), 256>>>(fw, fb);

    lstm_persistent<<<128, 256, LSTM_SMEM>>>();

    out_logsoftmax_tc<<<(T_LEN * BATCH) / 64, 256, OUT_SMEM>>>(ob, out);
}

// round 6
// speedup vs baseline: 2.9250x; 1.1766x over previous
#include <cuda_runtime.h>
#include <cuda_bf16.h>
#include <math.h>
#include <stdint.h>

#define T_LEN   64
#define BATCH   1024
#define VOCAB   128
#define HID     512
#define G4      2048
#define IMGFEAT 3600
#define KPAD    3648

// ---------------- helpers ----------------
__device__ __forceinline__ void cp16(uint32_t dst, const void* src) {
    size_t g = __cvta_generic_to_global(src);
    asm volatile("cp.async.cg.shared.global [%0], [%1], 16;" :: "r"(dst), "l"(g));
}
#define CP_COMMIT() asm volatile("cp.async.commit_group;" ::: "memory")
#define CP_WAIT(n)  asm volatile("cp.async.wait_group %0;" :: "n"(n) : "memory")

__device__ __forceinline__ uint32_t smem_u32(const void* p) {
    uint32_t a;
    asm("{ .reg .u64 t; cvta.to.shared.u64 t, %1; cvt.u32.u64 %0, t; }" : "=r"(a) : "l"(p));
    return a;
}

// m16n8k16 bf16 mma (row.col), fp32 accumulate
__device__ __forceinline__ void mma_bf16(float c[4],
                                         uint32_t a0, uint32_t a1, uint32_t a2, uint32_t a3,
                                         uint32_t b0, uint32_t b1) {
    asm volatile(
        "mma.sync.aligned.m16n8k16.row.col.f32.bf16.bf16.f32 "
        "{%0,%1,%2,%3}, {%4,%5,%6,%7}, {%8,%9}, {%0,%1,%2,%3};"
        : "+f"(c[0]), "+f"(c[1]), "+f"(c[2]), "+f"(c[3])
        : "r"(a0), "r"(a1), "r"(a2), "r"(a3), "r"(b0), "r"(b1));
}

// ---------------- scratch ----------------
__device__ float g_a1[BATCH * 8 * 32 * 32];
__device__ __nv_bfloat16 g_a2b[(size_t)BATCH * KPAD];      // conv2 out, K-padded (pad stays 0)
__device__ float g_e [BATCH * HID];
__device__ __nv_bfloat16 g_wt[(size_t)G4 * HID];           // hh_w^T  [2048,512]
__device__ __nv_bfloat16 g_xt[(size_t)G4 * VOCAB];         // xh_w^T  [2048,128]
__device__ __nv_bfloat16 g_owtb[VOCAB * HID];              // out_w^T [128,512]
__device__ __nv_bfloat16 g_fwt[(size_t)HID * KPAD];        // imgfc_w^T [512,3648] zero-padded
__device__ __nv_bfloat16 g_xb[(size_t)T_LEN * BATCH * VOCAB];
__device__ __nv_bfloat16 g_xgb[(size_t)T_LEN * BATCH * G4];// x-projection, bf16
__device__ float g_b4[G4];                                 // xh_b + hh_b
__device__ __nv_bfloat16 g_hsb[(size_t)T_LEN * BATCH * HID]; // h chain (bf16)
__device__ unsigned g_bar;

// ---------------- small kernels ----------------
__global__ void zero_bar() { g_bar = 0; }

__global__ void bias4(const float* __restrict__ xhb, const float* __restrict__ hhb) {
    int i = blockIdx.x * blockDim.x + threadIdx.x;
    if (i < G4) g_b4[i] = xhb[i] + hhb[i];
}

__global__ void cvt_inp(const float* __restrict__ inp) {
    int i = blockIdx.x * blockDim.x + threadIdx.x;
    const float2* s = (const float2*)inp;
    __nv_bfloat162* d = (__nv_bfloat162*)g_xb;
    d[i] = __float22bfloat162_rn(s[i]);
}

// transpose src[K][N] f32 -> dst[N][K] bf16 (divisible dims)
__global__ void transpose_bf16(const float* __restrict__ src, __nv_bfloat16* __restrict__ dst,
                               int K, int N) {
    __shared__ float ts[32][33];
    int bn = blockIdx.x * 32, bk = blockIdx.y * 32;
    int x = threadIdx.x, y = threadIdx.y;
#pragma unroll
    for (int i = 0; i < 32; i += 8)
        ts[y + i][x] = src[(size_t)(bk + y + i) * N + bn + x];
    __syncthreads();
#pragma unroll
    for (int i = 0; i < 32; i += 8)
        dst[(size_t)(bn + y + i) * K + bk + x] = __float2bfloat16_rn(ts[x][y + i]);
}

// imgfc weight: src [3600][512] f32 -> g_fwt [512][3648] bf16, zero pad k>=3600
__global__ void transpose_fw(const float* __restrict__ src) {
    __shared__ float ts[32][33];
    int bn = blockIdx.x * 32, bk = blockIdx.y * 32;
    int x = threadIdx.x, y = threadIdx.y;
#pragma unroll
    for (int i = 0; i < 32; i += 8) {
        int k = bk + y + i;
        ts[y + i][x] = (k < IMGFEAT) ? src[(size_t)k * HID + bn + x] : 0.f;
    }
    __syncthreads();
#pragma unroll
    for (int i = 0; i < 32; i += 8)
        g_fwt[(size_t)(bn + y + i) * KPAD + bk + x] = __float2bfloat16_rn(ts[x][y + i]);
}

// ---------------- conv1 (1->8,3x3,pad1)+relu+pool ----------------
__global__ void conv1_pool(const float* __restrict__ img,
                           const float* __restrict__ w,
                           const float* __restrict__ b) {
    int idx = blockIdx.x * blockDim.x + threadIdx.x;
    if (idx >= BATCH * 8 * 32 * 32) return;
    int px = idx & 31;
    int py = (idx >> 5) & 31;
    int oc = (idx >> 10) & 7;
    int bb = idx >> 13;
    const float* im = img + (size_t)bb * 64 * 64;
    const float* wk = w + oc * 9;
    float bias = b[oc];
    float m = -INFINITY;
#pragma unroll
    for (int dy = 0; dy < 2; dy++) {
#pragma unroll
        for (int dx = 0; dx < 2; dx++) {
            int y = py * 2 + dy, x = px * 2 + dx;
            float acc = bias;
#pragma unroll
            for (int ky = 0; ky < 3; ky++) {
                int iy = y + ky - 1;
                if ((unsigned)iy < 64u) {
#pragma unroll
                    for (int kx = 0; kx < 3; kx++) {
                        int ix = x + kx - 1;
                        if ((unsigned)ix < 64u)
                            acc += im[iy * 64 + ix] * wk[ky * 3 + kx];
                    }
                }
            }
            m = fmaxf(m, fmaxf(acc, 0.f));
        }
    }
    g_a1[idx] = m;
}

// ---------------- conv2 (8->16,5x5,pad1)+relu+pool -> bf16, K-padded layout ----------------
__global__ void conv2_pool(const float* __restrict__ w,
                           const float* __restrict__ b) {
    __shared__ float ws[16 * 8 * 25];
    for (int i = threadIdx.x; i < 16 * 8 * 25; i += blockDim.x) ws[i] = w[i];
    __syncthreads();
    int idx = blockIdx.x * blockDim.x + threadIdx.x;
    if (idx >= BATCH * 16 * 15 * 15) return;
    int px = idx % 15;
    int t  = idx / 15;
    int py = t % 15; t /= 15;
    int oc = t & 15;
    int bb = t >> 4;
    const float* a1b = g_a1 + (size_t)bb * 8 * 32 * 32;
    float bias = b[oc];
    float m = -INFINITY;
#pragma unroll
    for (int dy = 0; dy < 2; dy++) {
#pragma unroll
        for (int dx = 0; dx < 2; dx++) {
            int oy = py * 2 + dy, ox = px * 2 + dx;
            float acc = bias;
            for (int ic = 0; ic < 8; ic++) {
                const float* wp = ws + (oc * 8 + ic) * 25;
                const float* ap = a1b + ic * 1024;
#pragma unroll
                for (int ky = 0; ky < 5; ky++) {
                    int iy = oy + ky - 1;
                    if ((unsigned)iy < 32u) {
#pragma unroll
                        for (int kx = 0; kx < 5; kx++) {
                            int ix = ox + kx - 1;
                            if ((unsigned)ix < 32u)
                                acc += ap[iy * 32 + ix] * wp[ky * 5 + kx];
                        }
                    }
                }
            }
            m = fmaxf(m, fmaxf(acc, 0.f));
        }
    }
    g_a2b[(size_t)bb * KPAD + oc * 225 + py * 15 + px] = __float2bfloat16_rn(m);
}

// ---------------- imgfc: e = relu(a2b @ fwt^T + fb), bf16 mma ----------------
// Grid (HID/64=8, BATCH/128=8), 256 thr, CTA 128 rows x 64 cols, K=3648, chunk 64.
#define IF_AS 36
#define IF_ABUF (128 * IF_AS)     // u32
#define IF_BBUF (64 * IF_AS)
#define IMGFC_SMEM ((2 * IF_ABUF + 2 * IF_BBUF) * 4)
__global__ void __launch_bounds__(256, 1)
imgfc_mma(const float* __restrict__ fb) {
    extern __shared__ uint32_t smu[];
    uint32_t* As = smu;
    uint32_t* Bs = smu + 2 * IF_ABUF;
    const uint32_t a_u = smem_u32(As), b_u = smem_u32(Bs);
    const int tid = threadIdx.x, lane = tid & 31, wid = tid >> 5;
    const int wm = wid & 3, wn = wid >> 2;
    const int gq = lane >> 2, tq = lane & 3;
    const int bm = blockIdx.y * 128, bn = blockIdx.x * 64;

    float acc[2][4][4] = {};

    auto load_chunk = [&](int k0, int p) {
#pragma unroll
        for (int j = 0; j < 4; j++) {
            int idx = tid + j * 256;
            int r = idx >> 3, c4 = idx & 7;
            cp16(a_u + p * IF_ABUF * 4 + r * (IF_AS * 4) + c4 * 16,
                 g_a2b + (size_t)(bm + r) * KPAD + k0 + c4 * 8);
        }
#pragma unroll
        for (int j = 0; j < 2; j++) {
            int idx = tid + j * 256;
            int r = idx >> 3, c4 = idx & 7;
            cp16(b_u + p * IF_BBUF * 4 + r * (IF_AS * 4) + c4 * 16,
                 g_fwt + (size_t)(bn + r) * KPAD + k0 + c4 * 8);
        }
        CP_COMMIT();
    };

    const int NCH = KPAD / 64;   // 57
    load_chunk(0, 0);
    for (int c = 0; c < NCH; c++) {
        if (c + 1 < NCH) { load_chunk((c + 1) * 64, (c + 1) & 1); CP_WAIT(1); }
        else             { CP_WAIT(0); }
        __syncthreads();
        const uint32_t* Ab = As + (c & 1) * IF_ABUF;
        const uint32_t* Bb = Bs + (c & 1) * IF_BBUF;
#pragma unroll
        for (int ks = 0; ks < 4; ks++) {
            uint32_t afr[2][4];
#pragma unroll
            for (int mt = 0; mt < 2; mt++) {
                int r0 = wm * 32 + mt * 16 + gq;
                afr[mt][0] = Ab[(r0    ) * IF_AS + ks * 8 + tq    ];
                afr[mt][1] = Ab[(r0 + 8) * IF_AS + ks * 8 + tq    ];
                afr[mt][2] = Ab[(r0    ) * IF_AS + ks * 8 + tq + 4];
                afr[mt][3] = Ab[(r0 + 8) * IF_AS + ks * 8 + tq + 4];
            }
#pragma unroll
            for (int nt = 0; nt < 4; nt++) {
                int nrow = wn * 32 + nt * 8 + gq;
                uint32_t b0 = Bb[nrow * IF_AS + ks * 8 + tq    ];
                uint32_t b1 = Bb[nrow * IF_AS + ks * 8 + tq + 4];
#pragma unroll
                for (int mt = 0; mt < 2; mt++)
                    mma_bf16(acc[mt][nt], afr[mt][0], afr[mt][1], afr[mt][2], afr[mt][3], b0, b1);
            }
        }
        __syncthreads();
    }

#pragma unroll
    for (int mt = 0; mt < 2; mt++)
#pragma unroll
        for (int nt = 0; nt < 4; nt++) {
            int n = bn + wn * 32 + nt * 8 + tq * 2;
            int m = bm + wm * 32 + mt * 16 + gq;
            float b0 = fb[n], b1 = fb[n + 1];
            g_e[(size_t)m * HID + n]           = fmaxf(acc[mt][nt][0] + b0, 0.f);
            g_e[(size_t)m * HID + n + 1]       = fmaxf(acc[mt][nt][1] + b1, 0.f);
            g_e[(size_t)(m + 8) * HID + n]     = fmaxf(acc[mt][nt][2] + b0, 0.f);
            g_e[(size_t)(m + 8) * HID + n + 1] = fmaxf(acc[mt][nt][3] + b1, 0.f);
        }
}

// ---------------- xg = inp_bf16 @ xh_w^T, bf16 mma, bf16 out ----------------
// Grid (G4/128=16, 65536/128=512), 256 thr, CTA 128x128, K=128 one-shot.
#define XG_AS 68
#define XG_SMEM (2 * 128 * XG_AS * 4)
__global__ void __launch_bounds__(256, 1)
xg_mma() {
    extern __shared__ uint32_t smu[];
    uint32_t* As = smu;
    uint32_t* Bs = smu + 128 * XG_AS;
    const uint32_t a_u = smem_u32(As), b_u = smem_u32(Bs);
    const int tid = threadIdx.x, lane = tid & 31, wid = tid >> 5;
    const int wm = wid & 3, wn = wid >> 2;
    const int gq = lane >> 2, tq = lane & 3;
    const int bm = blockIdx.y * 128, bn = blockIdx.x * 128;

#pragma unroll
    for (int j = 0; j < 8; j++) {
        int idx = tid + j * 256;
        int r = idx >> 4, c4 = idx & 15;
        cp16(a_u + r * (XG_AS * 4) + c4 * 16, g_xb + (size_t)(bm + r) * VOCAB + c4 * 8);
    }
#pragma unroll
    for (int j = 0; j < 8; j++) {
        int idx = tid + j * 256;
        int r = idx >> 4, c4 = idx & 15;
        cp16(b_u + r * (XG_AS * 4) + c4 * 16, g_xt + (size_t)(bn + r) * VOCAB + c4 * 8);
    }
    CP_COMMIT(); CP_WAIT(0);
    __syncthreads();

    float acc[2][8][4] = {};
#pragma unroll
    for (int ks = 0; ks < 8; ks++) {
        uint32_t afr[2][4];
#pragma unroll
        for (int mt = 0; mt < 2; mt++) {
            int r0 = wm * 32 + mt * 16 + gq;
            afr[mt][0] = As[(r0    ) * XG_AS + ks * 8 + tq    ];
            afr[mt][1] = As[(r0 + 8) * XG_AS + ks * 8 + tq    ];
            afr[mt][2] = As[(r0    ) * XG_AS + ks * 8 + tq + 4];
            afr[mt][3] = As[(r0 + 8) * XG_AS + ks * 8 + tq + 4];
        }
#pragma unroll
        for (int nt = 0; nt < 8; nt++) {
            int nrow = wn * 64 + nt * 8 + gq;
            uint32_t b0 = Bs[nrow * XG_AS + ks * 8 + tq    ];
            uint32_t b1 = Bs[nrow * XG_AS + ks * 8 + tq + 4];
#pragma unroll
            for (int mt = 0; mt < 2; mt++)
                mma_bf16(acc[mt][nt], afr[mt][0], afr[mt][1], afr[mt][2], afr[mt][3], b0, b1);
        }
    }

#pragma unroll
    for (int mt = 0; mt < 2; mt++)
#pragma unroll
        for (int nt = 0; nt < 8; nt++) {
            int m = bm + wm * 32 + mt * 16 + gq;
            int n = bn + wn * 64 + nt * 8 + tq * 2;
            *(__nv_bfloat162*)&g_xgb[(size_t)m * G4 + n] =
                __float22bfloat162_rn(make_float2(acc[mt][nt][0], acc[mt][nt][1]));
            *(__nv_bfloat162*)&g_xgb[(size_t)(m + 8) * G4 + n] =
                __float22bfloat162_rn(make_float2(acc[mt][nt][2], acc[mt][nt][3]));
        }
}

// ---------------- persistent LSTM, bf16 mma, 512 threads ----------------
// 128 CTAs. CTA: 256 rows x 16 gate-cols x 4 gates. K=512 in 8 chunks of 64.
// Whh slice resident in SMEM; xg tile prefetched into SMEM per step; c in registers.
#define BHH_STRIDE 260
#define BHH_BYTES  (64 * BHH_STRIDE * 4)     // 66560
#define XG_STRIDE_U 36
#define XGS_BYTES  (256 * XG_STRIDE_U * 4)   // 36864
#define A_ST_U 36
#define ABUF_BYTES (256 * A_ST_U * 4)        // 36864
#define LSTM_SMEM (BHH_BYTES + XGS_BYTES + 2 * ABUF_BYTES)  // 177152

__global__ void __launch_bounds__(512, 1)
lstm_persistent() {
    extern __shared__ char sm[];
    uint32_t* Bhh = (uint32_t*)sm;
    uint32_t* Xgs = (uint32_t*)(sm + BHH_BYTES);
    char* Abuf = sm + BHH_BYTES + XGS_BYTES;
    const uint32_t xg_u = smem_u32(Xgs);
    const uint32_t a_u  = smem_u32(Abuf);
    const int tid = threadIdx.x, lane = tid & 31, wid = tid >> 5;
    const int wm = wid & 7, wn = wid >> 3;   // 8 m-groups x 32 rows, 2 n-groups x 8 cols
    const int gq = lane >> 2, tq = lane & 3;
    const int blk = blockIdx.x;
    const int n0 = (blk & 31) * 16;
    const int m0 = (blk >> 5) * 256;
    const int NCTA = 128;

    // resident Whh slice: 64 rows (g*16+n) x 512 K bf16
    for (int i = tid; i < 64 * 64; i += 512) {
        int row = i >> 6, c4 = i & 63;
        int g = row >> 4, n = row & 15;
        *(uint4*)((char*)Bhh + row * (BHH_STRIDE * 4) + c4 * 16) =
            *(const uint4*)((const char*)(g_wt + (size_t)(g * HID + n0 + n) * HID) + c4 * 16);
    }

    float creg[2][2][2];
#pragma unroll
    for (int mt = 0; mt < 2; mt++)
#pragma unroll
        for (int h = 0; h < 2; h++) creg[mt][h][0] = creg[mt][h][1] = 0.f;

    __syncthreads();

    const int nn = n0 + wn * 8 + tq * 2;
    unsigned bar_target = 0;

    for (int t = 0; t < T_LEN; t++) {
        // prefetch xg tile: 256 rows x (4 gates x 16 cols) bf16
        {
            const __nv_bfloat16* xgt = g_xgb + (size_t)t * BATCH * G4;
#pragma unroll
            for (int j = 0; j < 4; j++) {
                int idx = tid + j * 512;
                int r = idx >> 3, q = idx & 7;
                int g = q >> 1, h8 = q & 1;
                cp16(xg_u + r * (XG_STRIDE_U * 4) + q * 16,
                     xgt + (size_t)(m0 + r) * G4 + g * HID + n0 + h8 * 8);
            }
        }

        float acc[4][2][4];
#pragma unroll
        for (int g = 0; g < 4; g++)
#pragma unroll
            for (int mt = 0; mt < 2; mt++)
#pragma unroll
                for (int j = 0; j < 4; j++) acc[g][mt][j] = 0.f;

        if (t > 0) {
            const __nv_bfloat16* hin = g_hsb + (size_t)(t - 1) * BATCH * HID;
            auto load_chunk = [&](int kc, int p) {
                const uint32_t dst = a_u + (uint32_t)p * ABUF_BYTES;
#pragma unroll
                for (int j = 0; j < 4; j++) {
                    int idx = tid + j * 512;
                    int r = idx >> 3, c4 = idx & 7;
                    cp16(dst + r * (A_ST_U * 4) + c4 * 16,
                         hin + (size_t)(m0 + r) * HID + kc * 64 + c4 * 8);
                }
                CP_COMMIT();
            };
            load_chunk(0, 0);   // group also covers the xg prefetch above
            for (int c = 0; c < 8; c++) {
                if (c + 1 < 8) { load_chunk(c + 1, (c + 1) & 1); CP_WAIT(1); }
                else           { CP_WAIT(0); }
                __syncthreads();

                const uint32_t* Apk = (const uint32_t*)(Abuf + (c & 1) * ABUF_BYTES);
                const int kcol = c * 32;
#pragma unroll
                for (int ks = 0; ks < 4; ks++) {
                    uint32_t afr[2][4];
#pragma unroll
                    for (int mt = 0; mt < 2; mt++) {
                        int r0 = wm * 32 + mt * 16 + gq;
                        afr[mt][0] = Apk[(r0    ) * A_ST_U + ks * 8 + tq    ];
                        afr[mt][1] = Apk[(r0 + 8) * A_ST_U + ks * 8 + tq    ];
                        afr[mt][2] = Apk[(r0    ) * A_ST_U + ks * 8 + tq + 4];
                        afr[mt][3] = Apk[(r0 + 8) * A_ST_U + ks * 8 + tq + 4];
                    }
#pragma unroll
                    for (int g = 0; g < 4; g++) {
                        int nrow = g * 16 + wn * 8 + gq;
                        uint32_t b0 = Bhh[nrow * BHH_STRIDE + kcol + ks * 8 + tq    ];
                        uint32_t b1 = Bhh[nrow * BHH_STRIDE + kcol + ks * 8 + tq + 4];
#pragma unroll
                        for (int mt = 0; mt < 2; mt++)
                            mma_bf16(acc[g][mt], afr[mt][0], afr[mt][1], afr[mt][2], afr[mt][3], b0, b1);
                    }
                }
                __syncthreads();
            }
        } else {
            CP_COMMIT(); CP_WAIT(0);
            __syncthreads();
        }

        // ---- fused epilogue ----
        float2 b4i = *(const float2*)&g_b4[0 * HID + nn];
        float2 b4f = *(const float2*)&g_b4[1 * HID + nn];
        float2 b4g = *(const float2*)&g_b4[2 * HID + nn];
        float2 b4o = *(const float2*)&g_b4[3 * HID + nn];
        __nv_bfloat16* hs_t = g_hsb + (size_t)t * BATCH * HID;
        const int ncol = wn * 4 + tq;        // u32 column within 8-u32 gate block
#pragma unroll
        for (int mt = 0; mt < 2; mt++) {
#pragma unroll
            for (int half = 0; half < 2; half++) {
                int r = wm * 32 + mt * 16 + gq + half * 8;
                int m = m0 + r;
                float2 xi  = __bfloat1622float2(*(__nv_bfloat162*)&Xgs[r * XG_STRIDE_U + 0 * 8 + ncol]);
                float2 xf  = __bfloat1622float2(*(__nv_bfloat162*)&Xgs[r * XG_STRIDE_U + 1 * 8 + ncol]);
                float2 xg2 = __bfloat1622float2(*(__nv_bfloat162*)&Xgs[r * XG_STRIDE_U + 2 * 8 + ncol]);
                float2 xo  = __bfloat1622float2(*(__nv_bfloat162*)&Xgs[r * XG_STRIDE_U + 3 * 8 + ncol]);
                float2 ev = make_float2(0.f, 0.f);
                if (t == 0) ev = *(const float2*)&g_e[(size_t)m * HID + nn];
                float2 hv;
#pragma unroll
                for (int e = 0; e < 2; e++) {
                    float ee = e ? ev.y : ev.x;
                    float gi = acc[0][mt][half * 2 + e] + (e ? b4i.y : b4i.x) + (e ? xi.y : xi.x) + ee;
                    float gf = acc[1][mt][half * 2 + e] + (e ? b4f.y : b4f.x) + (e ? xf.y : xf.x) + ee;
                    float gg = acc[2][mt][half * 2 + e] + (e ? b4g.y : b4g.x) + (e ? xg2.y : xg2.x) + ee;
                    float go = acc[3][mt][half * 2 + e] + (e ? b4o.y : b4o.x) + (e ? xo.y : xo.x) + ee;
                    float i_ = 1.f / (1.f + expf(-gi));
                    float f_ = 1.f / (1.f + expf(-gf));
                    float g_ = tanhf(gg);
                    float o_ = 1.f / (1.f + expf(-go));
                    float cn = f_ * creg[mt][half][e] + i_ * g_;
                    creg[mt][half][e] = cn;
                    float hn = o_ * tanhf(cn);
                    if (e) hv.y = hn; else hv.x = hn;
                }
                *(__nv_bfloat162*)&hs_t[(size_t)m * HID + nn] = __float22bfloat162_rn(hv);
            }
        }

        // ---- grid barrier ----
        if (t + 1 < T_LEN) {
            bar_target += NCTA;
            __syncthreads();
            if (tid == 0) {
                __threadfence();
                atomicAdd(&g_bar, 1u);
                while (*(volatile unsigned*)&g_bar < bar_target) { }
                __threadfence();
            }
            __syncthreads();
        }
    }
}

// ---------------- out proj (bf16 mma) + fused log_softmax ----------------
// Grid 1024, 256 thr. CTA 64 rows x 128 cols, K=512 in 8 chunks of 64.
#define O_AS 36
#define O_ABUF (64 * O_AS)                    // u32
#define O_BBUF (128 * O_AS)
#define O_LSOFF (2 * O_ABUF + 2 * O_BBUF)
#define OUT_SMEM ((O_LSOFF + 64 * 132) * 4)
__global__ void __launch_bounds__(256, 1)
out_logsoftmax_b(const float* __restrict__ bias, float* __restrict__ out) {
    extern __shared__ uint32_t smu[];
    uint32_t* As = smu;
    uint32_t* Bs = smu + 2 * O_ABUF;
    float* Ls = (float*)(smu + O_LSOFF);
    const uint32_t a_u = smem_u32(As), b_u = smem_u32(Bs);
    const int tid = threadIdx.x, lane = tid & 31, wid = tid >> 5;
    const int wm = wid & 1, wn = wid >> 1;
    const int gq = lane >> 2, tq = lane & 3;
    const int bm = blockIdx.x * 64;

    float acc[2][4][4] = {};

    auto load_chunk = [&](int k0, int p) {
#pragma unroll
        for (int j = 0; j < 2; j++) {
            int idx = tid + j * 256;
            int r = idx >> 3, c4 = idx & 7;
            cp16(a_u + p * O_ABUF * 4 + r * (O_AS * 4) + c4 * 16,
                 g_hsb + (size_t)(bm + r) * HID + k0 + c4 * 8);
        }
#pragma unroll
        for (int j = 0; j < 4; j++) {
            int idx = tid + j * 256;
            int r = idx >> 3, c4 = idx & 7;
            cp16(b_u + p * O_BBUF * 4 + r * (O_AS * 4) + c4 * 16,
                 g_owtb + (size_t)r * HID + k0 + c4 * 8);
        }
        CP_COMMIT();
    };

    load_chunk(0, 0);
    for (int c = 0; c < 8; c++) {
        if (c + 1 < 8) { load_chunk((c + 1) * 64, (c + 1) & 1); CP_WAIT(1); }
        else           { CP_WAIT(0); }
        __syncthreads();
        const uint32_t* Ab = As + (c & 1) * O_ABUF;
        const uint32_t* Bb = Bs + (c & 1) * O_BBUF;
#pragma unroll
        for (int ks = 0; ks < 4; ks++) {
            uint32_t afr[2][4];
#pragma unroll
            for (int mt = 0; mt < 2; mt++) {
                int r0 = wm * 32 + mt * 16 + gq;
                afr[mt][0] = Ab[(r0    ) * O_AS + ks * 8 + tq    ];
                afr[mt][1] = Ab[(r0 + 8) * O_AS + ks * 8 + tq    ];
                afr[mt][2] = Ab[(r0    ) * O_AS + ks * 8 + tq + 4];
                afr[mt][3] = Ab[(r0 + 8) * O_AS + ks * 8 + tq + 4];
            }
#pragma unroll
            for (int nt = 0; nt < 4; nt++) {
                int nrow = wn * 32 + nt * 8 + gq;
                uint32_t b0 = Bb[nrow * O_AS + ks * 8 + tq    ];
                uint32_t b1 = Bb[nrow * O_AS + ks * 8 + tq + 4];
#pragma unroll
                for (int mt = 0; mt < 2; mt++)
                    mma_bf16(acc[mt][nt], afr[mt][0], afr[mt][1], afr[mt][2], afr[mt][3], b0, b1);
            }
        }
        __syncthreads();
    }

#pragma unroll
    for (int mt = 0; mt < 2; mt++)
#pragma unroll
        for (int nt = 0; nt < 4; nt++) {
            int row = wm * 32 + mt * 16 + gq;
            int col = wn * 32 + nt * 8 + tq * 2;
            float b0 = bias[col], b1 = bias[col + 1];
            Ls[(row    ) * 132 + col    ] = acc[mt][nt][0] + b0;
            Ls[(row    ) * 132 + col + 1] = acc[mt][nt][1] + b1;
            Ls[(row + 8) * 132 + col    ] = acc[mt][nt][2] + b0;
            Ls[(row + 8) * 132 + col + 1] = acc[mt][nt][3] + b1;
        }
    __syncthreads();

#pragma unroll
    for (int rr = 0; rr < 8; rr++) {
        int row = wid * 8 + rr;
        float v0 = Ls[row * 132 + lane], v1 = Ls[row * 132 + lane + 32];
        float v2 = Ls[row * 132 + lane + 64], v3 = Ls[row * 132 + lane + 96];
        float mx = fmaxf(fmaxf(v0, v1), fmaxf(v2, v3));
#pragma unroll
        for (int off = 16; off; off >>= 1) mx = fmaxf(mx, __shfl_xor_sync(0xffffffffu, mx, off));
        float s = expf(v0 - mx) + expf(v1 - mx) + expf(v2 - mx) + expf(v3 - mx);
#pragma unroll
        for (int off = 16; off; off >>= 1) s += __shfl_xor_sync(0xffffffffu, s, off);
        float lse = mx + logf(s);
        size_t base = (size_t)(bm + row) * VOCAB;
        out[base + lane]      = v0 - lse;
        out[base + lane + 32] = v1 - lse;
        out[base + lane + 64] = v2 - lse;
        out[base + lane + 96] = v3 - lse;
    }
}

// ---------------- launch ----------------
extern "C" void kernel_launch(void* const* d_in, const int* in_sizes, int n_in,
                              void* d_out, int out_size) {
    const float* inp = (const float*)d_in[0];
    const float* img = (const float*)d_in[1];
    const float* c1w = (const float*)d_in[2];
    const float* c1b = (const float*)d_in[3];
    const float* c2w = (const float*)d_in[4];
    const float* c2b = (const float*)d_in[5];
    const float* fw  = (const float*)d_in[6];
    const float* fb  = (const float*)d_in[7];
    const float* xhw = (const float*)d_in[8];
    const float* xhb = (const float*)d_in[9];
    const float* hhw = (const float*)d_in[10];
    const float* hhb = (const float*)d_in[11];
    const float* ow  = (const float*)d_in[12];
    const float* ob  = (const float*)d_in[13];
    float* out = (float*)d_out;

    cudaFuncSetAttribute(lstm_persistent, cudaFuncAttributeMaxDynamicSharedMemorySize, LSTM_SMEM);
    cudaFuncSetAttribute(out_logsoftmax_b, cudaFuncAttributeMaxDynamicSharedMemorySize, OUT_SMEM);
    cudaFuncSetAttribute(imgfc_mma, cudaFuncAttributeMaxDynamicSharedMemorySize, IMGFC_SMEM);
    cudaFuncSetAttribute(xg_mma, cudaFuncAttributeMaxDynamicSharedMemorySize, XG_SMEM);

    __nv_bfloat16* wt_p;  cudaGetSymbolAddress((void**)&wt_p,  g_wt);
    __nv_bfloat16* xt_p;  cudaGetSymbolAddress((void**)&xt_p,  g_xt);
    __nv_bfloat16* owt_p; cudaGetSymbolAddress((void**)&owt_p, g_owtb);

    zero_bar<<<1, 1>>>();
    bias4<<<G4 / 256, 256>>>(xhb, hhb);
    cvt_inp<<<(T_LEN * BATCH * VOCAB / 2) / 256, 256>>>(inp);
    transpose_bf16<<<dim3(G4 / 32, HID / 32), dim3(32, 8)>>>(hhw, wt_p, HID, G4);
    transpose_bf16<<<dim3(G4 / 32, VOCAB / 32), dim3(32, 8)>>>(xhw, xt_p, VOCAB, G4);
    transpose_bf16<<<dim3(VOCAB / 32, HID / 32), dim3(32, 8)>>>(ow, owt_p, HID, VOCAB);
    transpose_fw<<<dim3(HID / 32, KPAD / 32), dim3(32, 8)>>>(fw);
    conv1_pool<<<(BATCH * 8 * 32 * 32) / 256, 256>>>(img, c1w, c1b);
    conv2_pool<<<(BATCH * 16 * 15 * 15 + 255) / 256, 256>>>(c2w, c2b);
    imgfc_mma<<<dim3(HID / 64, BATCH / 128), 256, IMGFC_SMEM>>>(fb);
    xg_mma<<<dim3(G4 / 128, (T_LEN * BATCH) / 128), 256, XG_SMEM>>>();

    lstm_persistent<<<128, 512, LSTM_SMEM>>>();

    out_logsoftmax_b<<<(T_LEN * BATCH) / 64, 256, OUT_SMEM>>>(ob, out);
}

// round 7
// speedup vs baseline: 3.0976x; 1.0590x over previous
#include <cuda_runtime.h>
#include <cuda_bf16.h>
#include <math.h>
#include <stdint.h>

#define T_LEN   64
#define BATCH   1024
#define VOCAB   128
#define HID     512
#define G4      2048
#define IMGFEAT 3600
#define KPAD    3648

// ---------------- helpers ----------------
__device__ __forceinline__ void cp16(uint32_t dst, const void* src) {
    size_t g = __cvta_generic_to_global(src);
    asm volatile("cp.async.cg.shared.global [%0], [%1], 16;" :: "r"(dst), "l"(g));
}
#define CP_COMMIT() asm volatile("cp.async.commit_group;" ::: "memory")
#define CP_WAIT(n)  asm volatile("cp.async.wait_group %0;" :: "n"(n) : "memory")

__device__ __forceinline__ uint32_t smem_u32(const void* p) {
    uint32_t a;
    asm("{ .reg .u64 t; cvta.to.shared.u64 t, %1; cvt.u32.u64 %0, t; }" : "=r"(a) : "l"(p));
    return a;
}

__device__ __forceinline__ float ftanh(float x) {
    float y;
    asm("tanh.approx.f32 %0, %1;" : "=f"(y) : "f"(x));
    return y;
}
__device__ __forceinline__ float fsig(float x) {
    return 0.5f * ftanh(0.5f * x) + 0.5f;
}

// m16n8k16 bf16 mma (row.col), fp32 accumulate
__device__ __forceinline__ void mma_bf16(float c[4],
                                         uint32_t a0, uint32_t a1, uint32_t a2, uint32_t a3,
                                         uint32_t b0, uint32_t b1) {
    asm volatile(
        "mma.sync.aligned.m16n8k16.row.col.f32.bf16.bf16.f32 "
        "{%0,%1,%2,%3}, {%4,%5,%6,%7}, {%8,%9}, {%0,%1,%2,%3};"
        : "+f"(c[0]), "+f"(c[1]), "+f"(c[2]), "+f"(c[3])
        : "r"(a0), "r"(a1), "r"(a2), "r"(a3), "r"(b0), "r"(b1));
}

// ---------------- scratch ----------------
__device__ float g_a1[BATCH * 8 * 32 * 32];
__device__ __nv_bfloat16 g_a2b[(size_t)BATCH * KPAD];
__device__ float g_e [BATCH * HID];
__device__ __nv_bfloat16 g_wt[(size_t)G4 * HID];
__device__ __nv_bfloat16 g_xt[(size_t)G4 * VOCAB];
__device__ __nv_bfloat16 g_owtb[VOCAB * HID];
__device__ __nv_bfloat16 g_fwt[(size_t)HID * KPAD];
__device__ __nv_bfloat16 g_xb[(size_t)T_LEN * BATCH * VOCAB];
__device__ __nv_bfloat16 g_xgb[(size_t)T_LEN * BATCH * G4];
__device__ float g_b4[G4];
__device__ __nv_bfloat16 g_hsb[(size_t)T_LEN * BATCH * HID];
__device__ unsigned g_bar;

// ---------------- prep_all: one kernel, branch on blockIdx ----------------
// [0,16384)       cvt_inp       (4,194,304 bf162 elems)
// [16384,17408)   transpose hh  -> g_wt
// [17408,17664)   transpose xh  -> g_xt
// [17664,17728)   transpose ow  -> g_owtb
// [17728,19552)   transpose fw  -> g_fwt (zero-padded K)
// [19552,19560)   bias4
// 19560           zero_bar
#define PREP_BLOCKS 19561
__global__ void __launch_bounds__(256)
prep_all(const float* __restrict__ inp,
         const float* __restrict__ hhw, const float* __restrict__ xhw,
         const float* __restrict__ ow,  const float* __restrict__ fw,
         const float* __restrict__ xhb, const float* __restrict__ hhb) {
    const int blk = blockIdx.x, tid = threadIdx.x;
    if (blk < 16384) {
        int i = blk * 256 + tid;
        const float2* s = (const float2*)inp;
        ((__nv_bfloat162*)g_xb)[i] = __float22bfloat162_rn(s[i]);
        return;
    }
    __shared__ float ts[32][33];
    int x = tid & 31, y = (tid >> 5) * 4;   // 8 y-groups of 4 rows handled below via loop step 8
    // use classic (32,8) mapping: yy in {0,8,16,24}? keep original loop with y=tid>>5 (0..7)
    int yr = tid >> 5;                      // 0..7
    if (blk < 17408) {                      // hh: [512][2048] -> g_wt[2048][512]
        int b = blk - 16384;
        int bn = (b & 63) * 32, bk = (b >> 6) * 32;
#pragma unroll
        for (int i = 0; i < 32; i += 8)
            ts[yr + i][x] = hhw[(size_t)(bk + yr + i) * G4 + bn + x];
        __syncthreads();
#pragma unroll
        for (int i = 0; i < 32; i += 8)
            g_wt[(size_t)(bn + yr + i) * HID + bk + x] = __float2bfloat16_rn(ts[x][yr + i]);
    } else if (blk < 17664) {               // xh: [128][2048] -> g_xt[2048][128]
        int b = blk - 17408;
        int bn = (b & 63) * 32, bk = (b >> 6) * 32;
#pragma unroll
        for (int i = 0; i < 32; i += 8)
            ts[yr + i][x] = xhw[(size_t)(bk + yr + i) * G4 + bn + x];
        __syncthreads();
#pragma unroll
        for (int i = 0; i < 32; i += 8)
            g_xt[(size_t)(bn + yr + i) * VOCAB + bk + x] = __float2bfloat16_rn(ts[x][yr + i]);
    } else if (blk < 17728) {               // ow: [512][128] -> g_owtb[128][512]
        int b = blk - 17664;
        int bn = (b & 3) * 32, bk = (b >> 2) * 32;
#pragma unroll
        for (int i = 0; i < 32; i += 8)
            ts[yr + i][x] = ow[(size_t)(bk + yr + i) * VOCAB + bn + x];
        __syncthreads();
#pragma unroll
        for (int i = 0; i < 32; i += 8)
            g_owtb[(size_t)(bn + yr + i) * HID + bk + x] = __float2bfloat16_rn(ts[x][yr + i]);
    } else if (blk < 19552) {               // fw: [3600][512] -> g_fwt[512][3648] pad 0
        int b = blk - 17728;
        int bn = (b & 15) * 32, bk = (b >> 4) * 32;
#pragma unroll
        for (int i = 0; i < 32; i += 8) {
            int k = bk + yr + i;
            ts[yr + i][x] = (k < IMGFEAT) ? fw[(size_t)k * HID + bn + x] : 0.f;
        }
        __syncthreads();
#pragma unroll
        for (int i = 0; i < 32; i += 8)
            g_fwt[(size_t)(bn + yr + i) * KPAD + bk + x] = __float2bfloat16_rn(ts[x][yr + i]);
    } else if (blk < 19560) {
        int i = (blk - 19552) * 256 + tid;
        g_b4[i] = xhb[i] + hhb[i];
    } else {
        if (tid == 0) g_bar = 0;
    }
    (void)y;
}

// ---------------- conv1 (1->8,3x3,pad1)+relu+pool ----------------
__global__ void conv1_pool(const float* __restrict__ img,
                           const float* __restrict__ w,
                           const float* __restrict__ b) {
    int idx = blockIdx.x * blockDim.x + threadIdx.x;
    if (idx >= BATCH * 8 * 32 * 32) return;
    int px = idx & 31;
    int py = (idx >> 5) & 31;
    int oc = (idx >> 10) & 7;
    int bb = idx >> 13;
    const float* im = img + (size_t)bb * 64 * 64;
    const float* wk = w + oc * 9;
    float bias = b[oc];
    float m = -INFINITY;
#pragma unroll
    for (int dy = 0; dy < 2; dy++) {
#pragma unroll
        for (int dx = 0; dx < 2; dx++) {
            int y = py * 2 + dy, x = px * 2 + dx;
            float acc = bias;
#pragma unroll
            for (int ky = 0; ky < 3; ky++) {
                int iy = y + ky - 1;
                if ((unsigned)iy < 64u) {
#pragma unroll
                    for (int kx = 0; kx < 3; kx++) {
                        int ix = x + kx - 1;
                        if ((unsigned)ix < 64u)
                            acc += im[iy * 64 + ix] * wk[ky * 3 + kx];
                    }
                }
            }
            m = fmaxf(m, fmaxf(acc, 0.f));
        }
    }
    g_a1[idx] = m;
}

// ---------------- conv2 (8->16,5x5,pad1)+relu+pool -> bf16 ----------------
__global__ void conv2_pool(const float* __restrict__ w,
                           const float* __restrict__ b) {
    __shared__ float ws[16 * 8 * 25];
    for (int i = threadIdx.x; i < 16 * 8 * 25; i += blockDim.x) ws[i] = w[i];
    __syncthreads();
    int idx = blockIdx.x * blockDim.x + threadIdx.x;
    if (idx >= BATCH * 16 * 15 * 15) return;
    int px = idx % 15;
    int t  = idx / 15;
    int py = t % 15; t /= 15;
    int oc = t & 15;
    int bb = t >> 4;
    const float* a1b = g_a1 + (size_t)bb * 8 * 32 * 32;
    float bias = b[oc];
    float m = -INFINITY;
#pragma unroll
    for (int dy = 0; dy < 2; dy++) {
#pragma unroll
        for (int dx = 0; dx < 2; dx++) {
            int oy = py * 2 + dy, ox = px * 2 + dx;
            float acc = bias;
            for (int ic = 0; ic < 8; ic++) {
                const float* wp = ws + (oc * 8 + ic) * 25;
                const float* ap = a1b + ic * 1024;
#pragma unroll
                for (int ky = 0; ky < 5; ky++) {
                    int iy = oy + ky - 1;
                    if ((unsigned)iy < 32u) {
#pragma unroll
                        for (int kx = 0; kx < 5; kx++) {
                            int ix = ox + kx - 1;
                            if ((unsigned)ix < 32u)
                                acc += ap[iy * 32 + ix] * wp[ky * 5 + kx];
                        }
                    }
                }
            }
            m = fmaxf(m, fmaxf(acc, 0.f));
        }
    }
    g_a2b[(size_t)bb * KPAD + oc * 225 + py * 15 + px] = __float2bfloat16_rn(m);
}

// ---------------- imgfc (bf16 mma) ----------------
#define IF_AS 36
#define IF_ABUF (128 * IF_AS)
#define IF_BBUF (64 * IF_AS)
#define IMGFC_SMEM ((2 * IF_ABUF + 2 * IF_BBUF) * 4)
__global__ void __launch_bounds__(256, 1)
imgfc_mma(const float* __restrict__ fb) {
    extern __shared__ uint32_t smu[];
    uint32_t* As = smu;
    uint32_t* Bs = smu + 2 * IF_ABUF;
    const uint32_t a_u = smem_u32(As), b_u = smem_u32(Bs);
    const int tid = threadIdx.x, lane = tid & 31, wid = tid >> 5;
    const int wm = wid & 3, wn = wid >> 2;
    const int gq = lane >> 2, tq = lane & 3;
    const int bm = blockIdx.y * 128, bn = blockIdx.x * 64;

    float acc[2][4][4] = {};

    auto load_chunk = [&](int k0, int p) {
#pragma unroll
        for (int j = 0; j < 4; j++) {
            int idx = tid + j * 256;
            int r = idx >> 3, c4 = idx & 7;
            cp16(a_u + p * IF_ABUF * 4 + r * (IF_AS * 4) + c4 * 16,
                 g_a2b + (size_t)(bm + r) * KPAD + k0 + c4 * 8);
        }
#pragma unroll
        for (int j = 0; j < 2; j++) {
            int idx = tid + j * 256;
            int r = idx >> 3, c4 = idx & 7;
            cp16(b_u + p * IF_BBUF * 4 + r * (IF_AS * 4) + c4 * 16,
                 g_fwt + (size_t)(bn + r) * KPAD + k0 + c4 * 8);
        }
        CP_COMMIT();
    };

    const int NCH = KPAD / 64;
    load_chunk(0, 0);
    for (int c = 0; c < NCH; c++) {
        if (c + 1 < NCH) { load_chunk((c + 1) * 64, (c + 1) & 1); CP_WAIT(1); }
        else             { CP_WAIT(0); }
        __syncthreads();
        const uint32_t* Ab = As + (c & 1) * IF_ABUF;
        const uint32_t* Bb = Bs + (c & 1) * IF_BBUF;
#pragma unroll
        for (int ks = 0; ks < 4; ks++) {
            uint32_t afr[2][4];
#pragma unroll
            for (int mt = 0; mt < 2; mt++) {
                int r0 = wm * 32 + mt * 16 + gq;
                afr[mt][0] = Ab[(r0    ) * IF_AS + ks * 8 + tq    ];
                afr[mt][1] = Ab[(r0 + 8) * IF_AS + ks * 8 + tq    ];
                afr[mt][2] = Ab[(r0    ) * IF_AS + ks * 8 + tq + 4];
                afr[mt][3] = Ab[(r0 + 8) * IF_AS + ks * 8 + tq + 4];
            }
#pragma unroll
            for (int nt = 0; nt < 4; nt++) {
                int nrow = wn * 32 + nt * 8 + gq;
                uint32_t b0 = Bb[nrow * IF_AS + ks * 8 + tq    ];
                uint32_t b1 = Bb[nrow * IF_AS + ks * 8 + tq + 4];
#pragma unroll
                for (int mt = 0; mt < 2; mt++)
                    mma_bf16(acc[mt][nt], afr[mt][0], afr[mt][1], afr[mt][2], afr[mt][3], b0, b1);
            }
        }
        __syncthreads();
    }

#pragma unroll
    for (int mt = 0; mt < 2; mt++)
#pragma unroll
        for (int nt = 0; nt < 4; nt++) {
            int n = bn + wn * 32 + nt * 8 + tq * 2;
            int m = bm + wm * 32 + mt * 16 + gq;
            float b0 = fb[n], b1 = fb[n + 1];
            g_e[(size_t)m * HID + n]           = fmaxf(acc[mt][nt][0] + b0, 0.f);
            g_e[(size_t)m * HID + n + 1]       = fmaxf(acc[mt][nt][1] + b1, 0.f);
            g_e[(size_t)(m + 8) * HID + n]     = fmaxf(acc[mt][nt][2] + b0, 0.f);
            g_e[(size_t)(m + 8) * HID + n + 1] = fmaxf(acc[mt][nt][3] + b1, 0.f);
        }
}

// ---------------- xg = inp_bf16 @ xh_w^T ----------------
#define XG_AS 68
#define XG_SMEM (2 * 128 * XG_AS * 4)
__global__ void __launch_bounds__(256, 1)
xg_mma() {
    extern __shared__ uint32_t smu[];
    uint32_t* As = smu;
    uint32_t* Bs = smu + 128 * XG_AS;
    const uint32_t a_u = smem_u32(As), b_u = smem_u32(Bs);
    const int tid = threadIdx.x, lane = tid & 31, wid = tid >> 5;
    const int wm = wid & 3, wn = wid >> 2;
    const int gq = lane >> 2, tq = lane & 3;
    const int bm = blockIdx.y * 128, bn = blockIdx.x * 128;

#pragma unroll
    for (int j = 0; j < 8; j++) {
        int idx = tid + j * 256;
        int r = idx >> 4, c4 = idx & 15;
        cp16(a_u + r * (XG_AS * 4) + c4 * 16, g_xb + (size_t)(bm + r) * VOCAB + c4 * 8);
    }
#pragma unroll
    for (int j = 0; j < 8; j++) {
        int idx = tid + j * 256;
        int r = idx >> 4, c4 = idx & 15;
        cp16(b_u + r * (XG_AS * 4) + c4 * 16, g_xt + (size_t)(bn + r) * VOCAB + c4 * 8);
    }
    CP_COMMIT(); CP_WAIT(0);
    __syncthreads();

    float acc[2][8][4] = {};
#pragma unroll
    for (int ks = 0; ks < 8; ks++) {
        uint32_t afr[2][4];
#pragma unroll
        for (int mt = 0; mt < 2; mt++) {
            int r0 = wm * 32 + mt * 16 + gq;
            afr[mt][0] = As[(r0    ) * XG_AS + ks * 8 + tq    ];
            afr[mt][1] = As[(r0 + 8) * XG_AS + ks * 8 + tq    ];
            afr[mt][2] = As[(r0    ) * XG_AS + ks * 8 + tq + 4];
            afr[mt][3] = As[(r0 + 8) * XG_AS + ks * 8 + tq + 4];
        }
#pragma unroll
        for (int nt = 0; nt < 8; nt++) {
            int nrow = wn * 64 + nt * 8 + gq;
            uint32_t b0 = Bs[nrow * XG_AS + ks * 8 + tq    ];
            uint32_t b1 = Bs[nrow * XG_AS + ks * 8 + tq + 4];
#pragma unroll
            for (int mt = 0; mt < 2; mt++)
                mma_bf16(acc[mt][nt], afr[mt][0], afr[mt][1], afr[mt][2], afr[mt][3], b0, b1);
        }
    }

#pragma unroll
    for (int mt = 0; mt < 2; mt++)
#pragma unroll
        for (int nt = 0; nt < 8; nt++) {
            int m = bm + wm * 32 + mt * 16 + gq;
            int n = bn + wn * 64 + nt * 8 + tq * 2;
            *(__nv_bfloat162*)&g_xgb[(size_t)m * G4 + n] =
                __float22bfloat162_rn(make_float2(acc[mt][nt][0], acc[mt][nt][1]));
            *(__nv_bfloat162*)&g_xgb[(size_t)(m + 8) * G4 + n] =
                __float22bfloat162_rn(make_float2(acc[mt][nt][2], acc[mt][nt][3]));
        }
}

// ---------------- persistent LSTM ----------------
#define BHH_STRIDE 260
#define BHH_BYTES  (64 * BHH_STRIDE * 4)
#define XG_STRIDE_U 36
#define XGS_BYTES  (256 * XG_STRIDE_U * 4)
#define A_ST_U 36
#define ABUF_BYTES (256 * A_ST_U * 4)
#define LSTM_SMEM (BHH_BYTES + XGS_BYTES + 2 * ABUF_BYTES)

__global__ void __launch_bounds__(512, 1)
lstm_persistent() {
    extern __shared__ char sm[];
    uint32_t* Bhh = (uint32_t*)sm;
    uint32_t* Xgs = (uint32_t*)(sm + BHH_BYTES);
    char* Abuf = sm + BHH_BYTES + XGS_BYTES;
    const uint32_t xg_u = smem_u32(Xgs);
    const uint32_t a_u  = smem_u32(Abuf);
    const int tid = threadIdx.x, lane = tid & 31, wid = tid >> 5;
    const int wm = wid & 7, wn = wid >> 3;
    const int gq = lane >> 2, tq = lane & 3;
    const int blk = blockIdx.x;
    const int n0 = (blk & 31) * 16;
    const int m0 = (blk >> 5) * 256;
    const int NCTA = 128;

    for (int i = tid; i < 64 * 64; i += 512) {
        int row = i >> 6, c4 = i & 63;
        int g = row >> 4, n = row & 15;
        *(uint4*)((char*)Bhh + row * (BHH_STRIDE * 4) + c4 * 16) =
            *(const uint4*)((const char*)(g_wt + (size_t)(g * HID + n0 + n) * HID) + c4 * 16);
    }

    float creg[2][2][2];
#pragma unroll
    for (int mt = 0; mt < 2; mt++)
#pragma unroll
        for (int h = 0; h < 2; h++) creg[mt][h][0] = creg[mt][h][1] = 0.f;

    __syncthreads();

    const int nn = n0 + wn * 8 + tq * 2;
    unsigned bar_target = 0;

    for (int t = 0; t < T_LEN; t++) {
        const __nv_bfloat16* hin = g_hsb + (size_t)(t - 1) * BATCH * HID;

        auto load_chunk = [&](int kc, int p) {
            const uint32_t dst = a_u + (uint32_t)p * ABUF_BYTES;
#pragma unroll
            for (int j = 0; j < 4; j++) {
                int idx = tid + j * 512;
                int r = idx >> 3, c4 = idx & 7;
                cp16(dst + r * (A_ST_U * 4) + c4 * 16,
                     hin + (size_t)(m0 + r) * HID + kc * 64 + c4 * 8);
            }
            CP_COMMIT();
        };

        if (t > 0) load_chunk(0, 0);     // own group, ASAP

        // xg prefetch (joins next commit group)
        {
            const __nv_bfloat16* xgt = g_xgb + (size_t)t * BATCH * G4;
#pragma unroll
            for (int j = 0; j < 4; j++) {
                int idx = tid + j * 512;
                int r = idx >> 3, q = idx & 7;
                int g = q >> 1, h8 = q & 1;
                cp16(xg_u + r * (XG_STRIDE_U * 4) + q * 16,
                     xgt + (size_t)(m0 + r) * G4 + g * HID + n0 + h8 * 8);
            }
        }

        float acc[4][2][4];
#pragma unroll
        for (int g = 0; g < 4; g++)
#pragma unroll
            for (int mt = 0; mt < 2; mt++)
#pragma unroll
                for (int j = 0; j < 4; j++) acc[g][mt][j] = 0.f;

        if (t > 0) {
            for (int c = 0; c < 8; c++) {
                if (c + 1 < 8) { load_chunk(c + 1, (c + 1) & 1); CP_WAIT(1); }
                else           { CP_WAIT(0); }
                __syncthreads();

                const uint32_t* Apk = (const uint32_t*)(Abuf + (c & 1) * ABUF_BYTES);
                const int kcol = c * 32;
#pragma unroll
                for (int ks = 0; ks < 4; ks++) {
                    uint32_t afr[2][4];
#pragma unroll
                    for (int mt = 0; mt < 2; mt++) {
                        int r0 = wm * 32 + mt * 16 + gq;
                        afr[mt][0] = Apk[(r0    ) * A_ST_U + ks * 8 + tq    ];
                        afr[mt][1] = Apk[(r0 + 8) * A_ST_U + ks * 8 + tq    ];
                        afr[mt][2] = Apk[(r0    ) * A_ST_U + ks * 8 + tq + 4];
                        afr[mt][3] = Apk[(r0 + 8) * A_ST_U + ks * 8 + tq + 4];
                    }
#pragma unroll
                    for (int g = 0; g < 4; g++) {
                        int nrow = g * 16 + wn * 8 + gq;
                        uint32_t b0 = Bhh[nrow * BHH_STRIDE + kcol + ks * 8 + tq    ];
                        uint32_t b1 = Bhh[nrow * BHH_STRIDE + kcol + ks * 8 + tq + 4];
#pragma unroll
                        for (int mt = 0; mt < 2; mt++)
                            mma_bf16(acc[g][mt], afr[mt][0], afr[mt][1], afr[mt][2], afr[mt][3], b0, b1);
                    }
                }
                __syncthreads();
            }
        } else {
            CP_COMMIT(); CP_WAIT(0);
            __syncthreads();
        }

        // ---- fused epilogue (fast tanh/sigmoid) ----
        float2 b4i = *(const float2*)&g_b4[0 * HID + nn];
        float2 b4f = *(const float2*)&g_b4[1 * HID + nn];
        float2 b4g = *(const float2*)&g_b4[2 * HID + nn];
        float2 b4o = *(const float2*)&g_b4[3 * HID + nn];
        __nv_bfloat16* hs_t = g_hsb + (size_t)t * BATCH * HID;
        const int ncol = wn * 4 + tq;
#pragma unroll
        for (int mt = 0; mt < 2; mt++) {
#pragma unroll
            for (int half = 0; half < 2; half++) {
                int r = wm * 32 + mt * 16 + gq + half * 8;
                int m = m0 + r;
                float2 xi  = __bfloat1622float2(*(__nv_bfloat162*)&Xgs[r * XG_STRIDE_U + 0 * 8 + ncol]);
                float2 xf  = __bfloat1622float2(*(__nv_bfloat162*)&Xgs[r * XG_STRIDE_U + 1 * 8 + ncol]);
                float2 xg2 = __bfloat1622float2(*(__nv_bfloat162*)&Xgs[r * XG_STRIDE_U + 2 * 8 + ncol]);
                float2 xo  = __bfloat1622float2(*(__nv_bfloat162*)&Xgs[r * XG_STRIDE_U + 3 * 8 + ncol]);
                float2 ev = make_float2(0.f, 0.f);
                if (t == 0) ev = *(const float2*)&g_e[(size_t)m * HID + nn];
                float2 hv;
#pragma unroll
                for (int e = 0; e < 2; e++) {
                    float ee = e ? ev.y : ev.x;
                    float gi = acc[0][mt][half * 2 + e] + (e ? b4i.y : b4i.x) + (e ? xi.y : xi.x) + ee;
                    float gf = acc[1][mt][half * 2 + e] + (e ? b4f.y : b4f.x) + (e ? xf.y : xf.x) + ee;
                    float gg = acc[2][mt][half * 2 + e] + (e ? b4g.y : b4g.x) + (e ? xg2.y : xg2.x) + ee;
                    float go = acc[3][mt][half * 2 + e] + (e ? b4o.y : b4o.x) + (e ? xo.y : xo.x) + ee;
                    float i_ = fsig(gi);
                    float f_ = fsig(gf);
                    float g_ = ftanh(gg);
                    float o_ = fsig(go);
                    float cn = f_ * creg[mt][half][e] + i_ * g_;
                    creg[mt][half][e] = cn;
                    float hn = o_ * ftanh(cn);
                    if (e) hv.y = hn; else hv.x = hn;
                }
                *(__nv_bfloat162*)&hs_t[(size_t)m * HID + nn] = __float22bfloat162_rn(hv);
            }
        }

        // ---- grid barrier: release arrive, acquire spin ----
        if (t + 1 < T_LEN) {
            bar_target += NCTA;
            __syncthreads();
            if (tid == 0) {
                asm volatile("red.release.gpu.global.add.u32 [%0], 1;"
                             :: "l"(&g_bar) : "memory");
                unsigned v;
                do {
                    asm volatile("ld.acquire.gpu.global.u32 %0, [%1];"
                                 : "=r"(v) : "l"(&g_bar) : "memory");
                } while (v < bar_target);
            }
            __syncthreads();
        }
    }
}

// ---------------- out proj (bf16 mma) + fused log_softmax ----------------
#define O_AS 36
#define O_ABUF (64 * O_AS)
#define O_BBUF (128 * O_AS)
#define O_LSOFF (2 * O_ABUF + 2 * O_BBUF)
#define OUT_SMEM ((O_LSOFF + 64 * 132) * 4)
__global__ void __launch_bounds__(256, 1)
out_logsoftmax_b(const float* __restrict__ bias, float* __restrict__ out) {
    extern __shared__ uint32_t smu[];
    uint32_t* As = smu;
    uint32_t* Bs = smu + 2 * O_ABUF;
    float* Ls = (float*)(smu + O_LSOFF);
    const uint32_t a_u = smem_u32(As), b_u = smem_u32(Bs);
    const int tid = threadIdx.x, lane = tid & 31, wid = tid >> 5;
    const int wm = wid & 1, wn = wid >> 1;
    const int gq = lane >> 2, tq = lane & 3;
    const int bm = blockIdx.x * 64;

    float acc[2][4][4] = {};

    auto load_chunk = [&](int k0, int p) {
#pragma unroll
        for (int j = 0; j < 2; j++) {
            int idx = tid + j * 256;
            int r = idx >> 3, c4 = idx & 7;
            cp16(a_u + p * O_ABUF * 4 + r * (O_AS * 4) + c4 * 16,
                 g_hsb + (size_t)(bm + r) * HID + k0 + c4 * 8);
        }
#pragma unroll
        for (int j = 0; j < 4; j++) {
            int idx = tid + j * 256;
            int r = idx >> 3, c4 = idx & 7;
            cp16(b_u + p * O_BBUF * 4 + r * (O_AS * 4) + c4 * 16,
                 g_owtb + (size_t)r * HID + k0 + c4 * 8);
        }
        CP_COMMIT();
    };

    load_chunk(0, 0);
    for (int c = 0; c < 8; c++) {
        if (c + 1 < 8) { load_chunk((c + 1) * 64, (c + 1) & 1); CP_WAIT(1); }
        else           { CP_WAIT(0); }
        __syncthreads();
        const uint32_t* Ab = As + (c & 1) * O_ABUF;
        const uint32_t* Bb = Bs + (c & 1) * O_BBUF;
#pragma unroll
        for (int ks = 0; ks < 4; ks++) {
            uint32_t afr[2][4];
#pragma unroll
            for (int mt = 0; mt < 2; mt++) {
                int r0 = wm * 32 + mt * 16 + gq;
                afr[mt][0] = Ab[(r0    ) * O_AS + ks * 8 + tq    ];
                afr[mt][1] = Ab[(r0 + 8) * O_AS + ks * 8 + tq    ];
                afr[mt][2] = Ab[(r0    ) * O_AS + ks * 8 + tq + 4];
                afr[mt][3] = Ab[(r0 + 8) * O_AS + ks * 8 + tq + 4];
            }
#pragma unroll
            for (int nt = 0; nt < 4; nt++) {
                int nrow = wn * 32 + nt * 8 + gq;
                uint32_t b0 = Bb[nrow * O_AS + ks * 8 + tq    ];
                uint32_t b1 = Bb[nrow * O_AS + ks * 8 + tq + 4];
#pragma unroll
                for (int mt = 0; mt < 2; mt++)
                    mma_bf16(acc[mt][nt], afr[mt][0], afr[mt][1], afr[mt][2], afr[mt][3], b0, b1);
            }
        }
        __syncthreads();
    }

#pragma unroll
    for (int mt = 0; mt < 2; mt++)
#pragma unroll
        for (int nt = 0; nt < 4; nt++) {
            int row = wm * 32 + mt * 16 + gq;
            int col = wn * 32 + nt * 8 + tq * 2;
            float b0 = bias[col], b1 = bias[col + 1];
            Ls[(row    ) * 132 + col    ] = acc[mt][nt][0] + b0;
            Ls[(row    ) * 132 + col + 1] = acc[mt][nt][1] + b1;
            Ls[(row + 8) * 132 + col    ] = acc[mt][nt][2] + b0;
            Ls[(row + 8) * 132 + col + 1] = acc[mt][nt][3] + b1;
        }
    __syncthreads();

#pragma unroll
    for (int rr = 0; rr < 8; rr++) {
        int row = wid * 8 + rr;
        float v0 = Ls[row * 132 + lane], v1 = Ls[row * 132 + lane + 32];
        float v2 = Ls[row * 132 + lane + 64], v3 = Ls[row * 132 + lane + 96];
        float mx = fmaxf(fmaxf(v0, v1), fmaxf(v2, v3));
#pragma unroll
        for (int off = 16; off; off >>= 1) mx = fmaxf(mx, __shfl_xor_sync(0xffffffffu, mx, off));
        float s = expf(v0 - mx) + expf(v1 - mx) + expf(v2 - mx) + expf(v3 - mx);
#pragma unroll
        for (int off = 16; off; off >>= 1) s += __shfl_xor_sync(0xffffffffu, s, off);
        float lse = mx + logf(s);
        size_t base = (size_t)(bm + row) * VOCAB;
        out[base + lane]      = v0 - lse;
        out[base + lane + 32] = v1 - lse;
        out[base + lane + 64] = v2 - lse;
        out[base + lane + 96] = v3 - lse;
    }
}

// ---------------- launch ----------------
extern "C" void kernel_launch(void* const* d_in, const int* in_sizes, int n_in,
                              void* d_out, int out_size) {
    const float* inp = (const float*)d_in[0];
    const float* img = (const float*)d_in[1];
    const float* c1w = (const float*)d_in[2];
    const float* c1b = (const float*)d_in[3];
    const float* c2w = (const float*)d_in[4];
    const float* c2b = (const float*)d_in[5];
    const float* fw  = (const float*)d_in[6];
    const float* fb  = (const float*)d_in[7];
    const float* xhw = (const float*)d_in[8];
    const float* xhb = (const float*)d_in[9];
    const float* hhw = (const float*)d_in[10];
    const float* hhb = (const float*)d_in[11];
    const float* ow  = (const float*)d_in[12];
    const float* ob  = (const float*)d_in[13];
    float* out = (float*)d_out;

    cudaFuncSetAttribute(lstm_persistent, cudaFuncAttributeMaxDynamicSharedMemorySize, LSTM_SMEM);
    cudaFuncSetAttribute(out_logsoftmax_b, cudaFuncAttributeMaxDynamicSharedMemorySize, OUT_SMEM);
    cudaFuncSetAttribute(imgfc_mma, cudaFuncAttributeMaxDynamicSharedMemorySize, IMGFC_SMEM);
    cudaFuncSetAttribute(xg_mma, cudaFuncAttributeMaxDynamicSharedMemorySize, XG_SMEM);

    // launch order chosen so lstm_persistent is the 6th launch (ncu -s 5 -c 1)
    prep_all<<<PREP_BLOCKS, 256>>>(inp, hhw, xhw, ow, fw, xhb, hhb);            // 1
    conv1_pool<<<(BATCH * 8 * 32 * 32) / 256, 256>>>(img, c1w, c1b);            // 2
    conv2_pool<<<(BATCH * 16 * 15 * 15 + 255) / 256, 256>>>(c2w, c2b);          // 3
    imgfc_mma<<<dim3(HID / 64, BATCH / 128), 256, IMGFC_SMEM>>>(fb);            // 4
    xg_mma<<<dim3(G4 / 128, (T_LEN * BATCH) / 128), 256, XG_SMEM>>>();          // 5
    lstm_persistent<<<128, 512, LSTM_SMEM>>>();                                  // 6  <- profiled
    out_logsoftmax_b<<<(T_LEN * BATCH) / 64, 256, OUT_SMEM>>>(ob, out);          // 7
}